// round 11
// baseline (speedup 1.0000x reference)
#include <cuda_runtime.h>
#include <cuda_bf16.h>
#include <cuda_fp16.h>
#include <math.h>
#include <stdint.h>

#define Kc 65536
#define Dc 256
#define Oc 256
#define Bc 1024
#define TOPK 32
#define NCAND 48
#define NCAP 96
#define NTILES 512
#define TCAP 128
#define TWOD 512
#define SHIFT_FULL 491.25f
#define SHIFT_UNI  363.25f
#define HALF_D_LOG2PI 235.2482645f   // 0.5 * 256 * ln(2*pi)

// ---------------- device scratch ----------------
__device__ __nv_bfloat16 g_xb[(size_t)Bc * TWOD];        // 1 MB  [x | -0.5x^2]
__device__ __nv_bfloat16 g_wb[(size_t)Kc * TWOD];        // 64 MB [m*iv | iv]
__device__ float         g_bias[Kc];
__device__ __half        g_lh[(size_t)Bc * Kc];          // 128 MB shifted logits
__device__ __half        g_tmax[(size_t)Bc * NTILES];    // 1 MB per-row per-tile max (fp16)
__device__ int           g_flag;                          // 1 => stddev == 1 everywhere

__device__ __forceinline__ float neg_inf() { return __int_as_float(0xff800000); }

__device__ __forceinline__ uint32_t smem_u32(const void* p) {
    uint32_t a;
    asm("{ .reg .u64 t; cvta.to.shared.u64 t, %1; cvt.u32.u64 %0, t; }" : "=r"(a) : "l"(p));
    return a;
}
__device__ __forceinline__ void cp_async16(uint32_t dst, const void* src) {
    asm volatile("cp.async.cg.shared.global [%0], [%1], 16;" :: "r"(dst), "l"(src));
}
#define CP_COMMIT() asm volatile("cp.async.commit_group;" ::: "memory")
#define CP_WAIT(n)  asm volatile("cp.async.wait_group %0;" :: "n"(n) : "memory")

#define LDSM_X4(r, addr) \
    asm volatile("ldmatrix.sync.aligned.m8n8.x4.shared.b16 {%0,%1,%2,%3}, [%4];" \
        : "=r"((r)[0]), "=r"((r)[1]), "=r"((r)[2]), "=r"((r)[3]) : "r"(addr))

__device__ __forceinline__ void mma16816(float* c, const uint32_t* a, uint32_t b0, uint32_t b1) {
    asm volatile("mma.sync.aligned.m16n8k16.row.col.f32.bf16.bf16.f32 "
        "{%0,%1,%2,%3}, {%4,%5,%6,%7}, {%8,%9}, {%0,%1,%2,%3};"
        : "+f"(c[0]), "+f"(c[1]), "+f"(c[2]), "+f"(c[3])
        : "r"(a[0]), "r"(a[1]), "r"(a[2]), "r"(a[3]), "r"(b0), "r"(b1));
}

// both halves of a half2 word -> order-preserving 16-bit keys
__device__ __forceinline__ uint32_t key2(uint32_t h2) {
    uint32_t s = h2 & 0x80008000u;
    uint32_t m = 0x80008000u | ((s >> 15) * 0x7FFFu);
    return h2 ^ m;
}
__device__ __forceinline__ uint32_t hkey(uint32_t h) {   // single fp16 bits -> 16-bit key
    return h ^ ((h & 0x8000u) ? 0xFFFFu : 0x8000u);
}

// ---------------- prep kernels ----------------
__global__ void prep_x_kernel(const float* __restrict__ x) {
    int b = blockIdx.x, d = threadIdx.x;
    float v = x[b * Dc + d];
    g_xb[(size_t)b * TWOD + d]      = __float2bfloat16(v);
    g_xb[(size_t)b * TWOD + Dc + d] = __float2bfloat16(-0.5f * v * v);
    if (b == 0 && d == 0) g_flag = 1;   // reset each launch (graph-replay safe)
}

// warp per k-row, lane handles 8 elements; writes only the m*iv half (32 MB)
__global__ void __launch_bounds__(256) prep_w_kernel(const float* __restrict__ mean,
                                                     const float* __restrict__ stddev) {
    int warp = threadIdx.x >> 5, lane = threadIdx.x & 31;
    int k = blockIdx.x * 8 + warp;
    int e = lane * 8;
    const float* mp = mean   + (size_t)k * Dc + e;
    const float* sp = stddev + (size_t)k * Dc + e;
    float4 ma = *(const float4*)mp,      mb = *(const float4*)(mp + 4);
    float4 sa = *(const float4*)sp,      sb = *(const float4*)(sp + 4);

    bool nonuni = (sa.x != 1.0f) | (sa.y != 1.0f) | (sa.z != 1.0f) | (sa.w != 1.0f) |
                  (sb.x != 1.0f) | (sb.y != 1.0f) | (sb.z != 1.0f) | (sb.w != 1.0f);
    if (nonuni) g_flag = 0;

    float m8[8] = {ma.x, ma.y, ma.z, ma.w, mb.x, mb.y, mb.z, mb.w};
    float s8[8] = {sa.x, sa.y, sa.z, sa.w, sb.x, sb.y, sb.z, sb.w};
    float part = 0.0f;
    __nv_bfloat16 w8[8];
    #pragma unroll
    for (int i = 0; i < 8; i++) {
        float iv = 1.0f / (s8[i] * s8[i]);
        float miv = m8[i] * iv;
        w8[i] = __float2bfloat16(miv);
        part = fmaf(-0.5f * m8[i], miv, part);
    }
    if (nonuni) {
        #pragma unroll
        for (int i = 0; i < 8; i++) part -= logf(s8[i]);
    }
    *(uint4*)&g_wb[(size_t)k * TWOD + e] = *(uint4*)w8;

    #pragma unroll
    for (int off = 16; off > 0; off >>= 1)
        part += __shfl_xor_sync(0xffffffffu, part, off);
    if (lane == 0) g_bias[k] = part - HALF_D_LOG2PI;
}

// fix-up: writes the iv half; runs only when some stddev != 1
__global__ void __launch_bounds__(256) prep_w_fix_kernel(const float* __restrict__ stddev) {
    if (g_flag) return;
    int warp = threadIdx.x >> 5, lane = threadIdx.x & 31;
    int k = blockIdx.x * 8 + warp;
    int e = lane * 8;
    const float* sp = stddev + (size_t)k * Dc + e;
    float4 sa = *(const float4*)sp, sb = *(const float4*)(sp + 4);
    float s8[8] = {sa.x, sa.y, sa.z, sa.w, sb.x, sb.y, sb.z, sb.w};
    __nv_bfloat16 w8[8];
    #pragma unroll
    for (int i = 0; i < 8; i++)
        w8[i] = __float2bfloat16(1.0f / (s8[i] * s8[i]));
    *(uint4*)&g_wb[(size_t)k * TWOD + Dc + e] = *(uint4*)w8;
}

// ---------------- mma.sync bf16 GEMM (+ per-tile row max) ----------------
#define NSTAGE 4
#define ROWB   80
#define STAGE_BYTES (128 * ROWB * 2)   // A + B per stage = 20480
#define GEMM_SMEM (NSTAGE * STAGE_BYTES)
#define STGROW 272                      // staging row stride (bytes)

__device__ __forceinline__ void load_stage(uint32_t sbase, int st, int m0, int n0, int k0, int tid) {
    uint32_t ab = sbase + st * STAGE_BYTES;
    uint32_t bb = ab + 128 * ROWB;
    #pragma unroll
    for (int i = 0; i < 2; i++) {
        int lin = tid + (i << 8);
        int row = lin >> 2, ch = lin & 3;
        cp_async16(ab + row * ROWB + ch * 16, g_xb + (size_t)(m0 + row) * TWOD + k0 + ch * 8);
        cp_async16(bb + row * ROWB + ch * 16, g_wb + (size_t)(n0 + row) * TWOD + k0 + ch * 8);
    }
    CP_COMMIT();
}

__global__ void __launch_bounds__(256, 2) gemm_kernel() {
    extern __shared__ char smem[];
    __shared__ float smax[128][4];
    uint32_t sbase = smem_u32(smem);
    int tid = threadIdx.x, wid = tid >> 5, lane = tid & 31;
    int m0 = blockIdx.y * 128;
    int n0 = blockIdx.x * 128;
    int wm = wid >> 2, wn = wid & 3;

    int uni = g_flag;
    int KT = uni ? 8 : 16;
    float SHIFTV = uni ? SHIFT_UNI : SHIFT_FULL;

    float acc[4][4][4];
    #pragma unroll
    for (int mt = 0; mt < 4; mt++)
        #pragma unroll
        for (int nt = 0; nt < 4; nt++)
            #pragma unroll
            for (int q = 0; q < 4; q++) acc[mt][nt][q] = 0.0f;

    load_stage(sbase, 0, m0, n0, 0, tid);
    load_stage(sbase, 1, m0, n0, 32, tid);
    load_stage(sbase, 2, m0, n0, 64, tid);

    uint32_t a_row = (uint32_t)(wm * 64 + (lane & 15));
    uint32_t a_off = a_row * ROWB + ((lane >> 4) << 4);
    uint32_t b_row = (uint32_t)(wn * 32 + (lane & 7) + ((lane >> 4) << 3));
    uint32_t b_off = b_row * ROWB + (((lane >> 3) & 1) << 4);

    #pragma unroll 1
    for (int it = 0; it < KT; it++) {
        CP_WAIT(2);
        __syncthreads();
        if (it + 3 < KT) load_stage(sbase, (it + 3) % NSTAGE, m0, n0, (it + 3) * 32, tid);
        else CP_COMMIT();

        int st = it % NSTAGE;
        uint32_t ab = sbase + st * STAGE_BYTES;
        uint32_t bb = ab + 128 * ROWB;

        #pragma unroll
        for (int ks = 0; ks < 2; ks++) {
            uint32_t afr[4][4];
            #pragma unroll
            for (int mt = 0; mt < 4; mt++)
                LDSM_X4(afr[mt], ab + a_off + mt * (16 * ROWB) + ks * 32);
            uint32_t bfr[2][4];
            #pragma unroll
            for (int np = 0; np < 2; np++)
                LDSM_X4(bfr[np], bb + b_off + np * (16 * ROWB) + ks * 32);
            #pragma unroll
            for (int mt = 0; mt < 4; mt++)
                #pragma unroll
                for (int nt = 0; nt < 4; nt++)
                    mma16816(acc[mt][nt], afr[mt],
                             bfr[nt >> 1][(nt & 1) * 2], bfr[nt >> 1][(nt & 1) * 2 + 1]);
        }
    }
    CP_WAIT(0);
    __syncthreads();   // all ldmatrix done: staging may overwrite pipeline smem

    const float NI = neg_inf();
    float rmA[4], rmB[4];
    #pragma unroll
    for (int mt = 0; mt < 4; mt++) { rmA[mt] = NI; rmB[mt] = NI; }

    // stage converted half2 into smem (conflict-free: 272B row stride)
    #pragma unroll
    for (int nt = 0; nt < 4; nt++) {
        int col = wn * 32 + nt * 8 + (lane & 3) * 2;
        float2 bb2 = *(const float2*)&g_bias[n0 + col];
        float bx = bb2.x + SHIFTV, by = bb2.y + SHIFTV;
        #pragma unroll
        for (int mt = 0; mt < 4; mt++) {
            int rowl = wm * 64 + mt * 16 + (lane >> 2);
            float a0 = acc[mt][nt][0] + bx, a1 = acc[mt][nt][1] + by;
            float a2 = acc[mt][nt][2] + bx, a3 = acc[mt][nt][3] + by;
            rmA[mt] = fmaxf(rmA[mt], fmaxf(a0, a1));
            rmB[mt] = fmaxf(rmB[mt], fmaxf(a2, a3));
            *(__half2*)(smem + rowl * STGROW + col * 2)       = __floats2half2_rn(a0, a1);
            *(__half2*)(smem + (rowl + 8) * STGROW + col * 2) = __floats2half2_rn(a2, a3);
        }
    }

    #pragma unroll
    for (int mt = 0; mt < 4; mt++) {
        #pragma unroll
        for (int off = 1; off < 4; off <<= 1) {
            rmA[mt] = fmaxf(rmA[mt], __shfl_xor_sync(0xffffffffu, rmA[mt], off));
            rmB[mt] = fmaxf(rmB[mt], __shfl_xor_sync(0xffffffffu, rmB[mt], off));
        }
        if ((lane & 3) == 0) {
            int lr = wm * 64 + mt * 16 + (lane >> 2);
            smax[lr][wn]     = rmA[mt];
            smax[lr + 8][wn] = rmB[mt];
        }
    }
    __syncthreads();

    // coalesced copy-out: 128 rows x 256B = 2048 uint4
    #pragma unroll
    for (int i = 0; i < 8; i++) {
        int lin = tid + (i << 8);
        int r = lin >> 4, q = lin & 15;
        uint4 v = *(const uint4*)(smem + r * STGROW + q * 16);
        *(uint4*)(g_lh + (size_t)(m0 + r) * Kc + n0 + q * 8) = v;
    }

    if (tid < 128) {
        float m = fmaxf(fmaxf(smax[tid][0], smax[tid][1]), fmaxf(smax[tid][2], smax[tid][3]));
        g_tmax[(size_t)(m0 + tid) * NTILES + blockIdx.x] = __float2half(m);
    }
}

// ---------------- topk: tile-max guided selection + exact rescore ----------------
__global__ void __launch_bounds__(1024) topk_kernel(const float* __restrict__ x,
                                                    const float* __restrict__ mean,
                                                    const float* __restrict__ stddev,
                                                    const float* __restrict__ outputs,
                                                    float* __restrict__ out) {
    int b = blockIdx.x, t = threadIdx.x;
    int lane = t & 31, warp = t >> 5;
    const float NI = neg_inf();
    int uni = g_flag;

    __shared__ int   s_tiles[TCAP];
    __shared__ int   s_nt, s_cnt;
    __shared__ int   sred[32];
    __shared__ uint32_t s_cand[NCAP];
    __shared__ float s_clp[NCAP];
    __shared__ float s_fv[TOPK];
    __shared__ int   s_fi[TOPK];
    __shared__ float s_w[TOPK];
    __shared__ float part[4 * 256];

    // ---- stage 1: tile-max threshold via block-vote binary search (16-bit keys) ----
    uint32_t tk = (t < NTILES)
        ? hkey((uint32_t)__half_as_ushort(g_tmax[(size_t)b * NTILES + t])) : 0u;
    uint32_t cur = 0;
    #pragma unroll 1
    for (int bit = 15; bit >= 0; --bit) {
        uint32_t T = cur | (1u << bit);
        int n = __syncthreads_count(tk >= T);
        if (n >= NCAND) cur = T;
    }
    if (t == 0) s_nt = 0;
    __syncthreads();
    if (t < NTILES && tk >= cur) {
        int p = atomicAdd(&s_nt, 1);
        if (p < TCAP) s_tiles[p] = t;
    }
    __syncthreads();
    int ntl = s_nt < TCAP ? s_nt : TCAP;
    int total = ntl * 64;          // u32 words across selected tiles

    // ---- stage 2: gather selected tiles into registers as 16-bit keys ----
    const uint32_t* row32 = (const uint32_t*)(g_lh + (size_t)b * Kc);
    uint32_t u[8];
    #pragma unroll
    for (int i = 0; i < 8; i++) {
        int w = t + (i << 10);
        if (w < total) {
            int tile = s_tiles[w >> 6];
            u[i] = key2(row32[tile * 64 + (w & 63)]);
        } else {
            u[i] = 0x03FF03FFu;    // key of -inf in both halves
        }
    }

    // ---- stage 3: exact 16-bit threshold via block-sum binary search ----
    uint32_t cur16 = 0;
    #pragma unroll 1
    for (int bit = 15; bit >= 0; --bit) {
        uint32_t T = cur16 | (1u << bit);
        int c = 0;
        #pragma unroll
        for (int i = 0; i < 8; i++)
            c += ((u[i] & 0xFFFFu) >= T) + ((u[i] >> 16) >= T);
        #pragma unroll
        for (int off = 16; off > 0; off >>= 1)
            c += __shfl_xor_sync(0xffffffffu, c, off);
        __syncthreads();
        if (lane == 0) sred[warp] = c;
        __syncthreads();
        int n = 0;
        #pragma unroll
        for (int w = 0; w < 32; w++) n += sred[w];
        if (n >= NCAND) cur16 = T;
    }
    if (t == 0) s_cnt = 0;
    if (t < NCAP) s_clp[t] = NI;
    __syncthreads();

    // ---- stage 4: collect candidates ----
    #pragma unroll
    for (int i = 0; i < 8; i++) {
        int w = t + (i << 10);
        if (w < total) {
            uint32_t klo = u[i] & 0xFFFFu, khi = u[i] >> 16;
            uint32_t idx = (uint32_t)(s_tiles[w >> 6] * 128 + (w & 63) * 2);
            if (klo >= cur16) {
                int p = atomicAdd(&s_cnt, 1);
                if (p < NCAP) s_cand[p] = (klo << 16) | idx;
            }
            if (khi >= cur16) {
                int p = atomicAdd(&s_cnt, 1);
                if (p < NCAP) s_cand[p] = (khi << 16) | (idx + 1);
            }
        }
    }
    __syncthreads();
    int M = s_cnt < NCAP ? s_cnt : NCAP;

    // ---- exact fp32 rescore (one warp per candidate) ----
    for (int cc = warp; cc < M; cc += 32) {
        int c = (int)(s_cand[cc] & 0xFFFFu);
        float sq = 0.0f, sl = 0.0f;
        if (uni) {
            #pragma unroll
            for (int jj = 0; jj < 8; jj++) {
                int d = lane + (jj << 5);
                float m  = mean[(size_t)c * Dc + d];
                float xv = x[(size_t)b * Dc + d];
                float df = xv - m;
                sq = fmaf(df, df, sq);
            }
        } else {
            #pragma unroll
            for (int jj = 0; jj < 8; jj++) {
                int d = lane + (jj << 5);
                float m  = mean[(size_t)c * Dc + d];
                float sd = stddev[(size_t)c * Dc + d];
                float xv = x[(size_t)b * Dc + d];
                float iv = 1.0f / (sd * sd);
                float df = xv - m;
                sq = fmaf(df * df, iv, sq);
                sl += logf(sd);
            }
        }
        #pragma unroll
        for (int off = 16; off > 0; off >>= 1) {
            sq += __shfl_xor_sync(0xffffffffu, sq, off);
            sl += __shfl_xor_sync(0xffffffffu, sl, off);
        }
        if (lane == 0) s_clp[cc] = -0.5f * sq - sl - HALF_D_LOG2PI;
    }
    __syncthreads();

    // ---- exact top-32 of up to 96 rescored values (warp 0, 3 slots/lane) ----
    if (warp == 0) {
        float va[3]; int ia[3];
        #pragma unroll
        for (int q = 0; q < 3; q++) { ia[q] = lane + q * 32; va[q] = s_clp[ia[q]]; }
        for (int r = 0; r < TOPK; r++) {
            float m = va[0]; int mi = ia[0];
            if (va[1] > m) { m = va[1]; mi = ia[1]; }
            if (va[2] > m) { m = va[2]; mi = ia[2]; }
            float bm = m; int bi = mi;
            #pragma unroll
            for (int off = 16; off > 0; off >>= 1) {
                float ov = __shfl_down_sync(0xffffffffu, bm, off);
                int   oi = __shfl_down_sync(0xffffffffu, bi, off);
                if (ov > bm) { bm = ov; bi = oi; }
            }
            bm = __shfl_sync(0xffffffffu, bm, 0);
            bi = __shfl_sync(0xffffffffu, bi, 0);
            if (lane == 0) { s_fv[r] = bm; s_fi[r] = (int)(s_cand[bi] & 0xFFFFu); }
            #pragma unroll
            for (int q = 0; q < 3; q++) if (ia[q] == bi) va[q] = NI;
        }
    }
    __syncthreads();

    if (t < TOPK) {
        float e = expf(s_fv[t] - s_fv[0]);
        float s = e;
        #pragma unroll
        for (int off = 16; off > 0; off >>= 1)
            s += __shfl_xor_sync(0xffffffffu, s, off);
        s_w[t] = e / s;
    }
    __syncthreads();

    int o = t & 255, g = t >> 8;   // g in {0..3}
    float p = 0.0f;
    #pragma unroll
    for (int j = 0; j < 8; j++) {
        int jj = g * 8 + j;
        p = fmaf(s_w[jj], outputs[(size_t)s_fi[jj] * Oc + o], p);
    }
    part[g * 256 + o] = p;
    __syncthreads();
    if (t < 256)
        out[(size_t)b * Oc + t] = part[t] + part[256 + t] + part[512 + t] + part[768 + t];
}

// ---------------- launch ----------------
extern "C" void kernel_launch(void* const* d_in, const int* in_sizes, int n_in,
                              void* d_out, int out_size) {
    const float* x       = (const float*)d_in[0];
    const float* mean    = (const float*)d_in[1];
    const float* stddev  = (const float*)d_in[2];
    const float* outputs = (const float*)d_in[3];
    float* out = (float*)d_out;

    cudaFuncSetAttribute(gemm_kernel, cudaFuncAttributeMaxDynamicSharedMemorySize, GEMM_SMEM);

    prep_x_kernel<<<Bc, Dc>>>(x);
    prep_w_kernel<<<Kc / 8, 256>>>(mean, stddev);
    prep_w_fix_kernel<<<Kc / 8, 256>>>(stddev);
    gemm_kernel<<<dim3(Kc / 128, Bc / 128), 256, GEMM_SMEM>>>();
    topk_kernel<<<Bc, 1024>>>(x, mean, stddev, outputs, out);
}

// round 12
// speedup vs baseline: 1.2400x; 1.2400x over previous
#include <cuda_runtime.h>
#include <cuda_bf16.h>
#include <cuda_fp16.h>
#include <math.h>
#include <stdint.h>

#define Kc 65536
#define Dc 256
#define Oc 256
#define Bc 1024
#define TOPK 32
#define NCAND 48
#define NCAP 96
#define NTILES 512
#define TCAP 128
#define TWOD 512
#define SHIFT_FULL 491.25f
#define SHIFT_UNI  363.25f
#define HALF_D_LOG2PI 235.2482645f   // 0.5 * 256 * ln(2*pi)

// ---------------- device scratch ----------------
__device__ __nv_bfloat16 g_xb[(size_t)Bc * TWOD];        // 1 MB  [x | -0.5x^2]
__device__ __nv_bfloat16 g_wb[(size_t)Kc * TWOD];        // 64 MB [m*iv | iv]
__device__ float         g_bias[Kc];
__device__ __half        g_lh[(size_t)Bc * Kc];          // 128 MB shifted logits
__device__ __half        g_tmax[(size_t)Bc * NTILES];    // 1 MB per-row per-tile max (fp16)
__device__ int           g_flag;                          // 1 => stddev == 1 everywhere

__device__ __forceinline__ float neg_inf() { return __int_as_float(0xff800000); }

__device__ __forceinline__ uint32_t smem_u32(const void* p) {
    uint32_t a;
    asm("{ .reg .u64 t; cvta.to.shared.u64 t, %1; cvt.u32.u64 %0, t; }" : "=r"(a) : "l"(p));
    return a;
}
__device__ __forceinline__ void cp_async16(uint32_t dst, const void* src) {
    asm volatile("cp.async.cg.shared.global [%0], [%1], 16;" :: "r"(dst), "l"(src));
}
#define CP_COMMIT() asm volatile("cp.async.commit_group;" ::: "memory")
#define CP_WAIT(n)  asm volatile("cp.async.wait_group %0;" :: "n"(n) : "memory")

#define LDSM_X4(r, addr) \
    asm volatile("ldmatrix.sync.aligned.m8n8.x4.shared.b16 {%0,%1,%2,%3}, [%4];" \
        : "=r"((r)[0]), "=r"((r)[1]), "=r"((r)[2]), "=r"((r)[3]) : "r"(addr))

__device__ __forceinline__ void mma16816(float* c, const uint32_t* a, uint32_t b0, uint32_t b1) {
    asm volatile("mma.sync.aligned.m16n8k16.row.col.f32.bf16.bf16.f32 "
        "{%0,%1,%2,%3}, {%4,%5,%6,%7}, {%8,%9}, {%0,%1,%2,%3};"
        : "+f"(c[0]), "+f"(c[1]), "+f"(c[2]), "+f"(c[3])
        : "r"(a[0]), "r"(a[1]), "r"(a[2]), "r"(a[3]), "r"(b0), "r"(b1));
}

// both halves of a half2 word -> order-preserving 16-bit keys
__device__ __forceinline__ uint32_t key2(uint32_t h2) {
    uint32_t s = h2 & 0x80008000u;
    uint32_t m = 0x80008000u | ((s >> 15) * 0x7FFFu);
    return h2 ^ m;
}
__device__ __forceinline__ uint32_t hkey(uint32_t h) {   // single fp16 bits -> 16-bit key
    return h ^ ((h & 0x8000u) ? 0xFFFFu : 0x8000u);
}

// ---------------- prep kernels ----------------
__global__ void prep_x_kernel(const float* __restrict__ x) {
    int b = blockIdx.x, d = threadIdx.x;
    float v = x[b * Dc + d];
    g_xb[(size_t)b * TWOD + d]      = __float2bfloat16(v);
    g_xb[(size_t)b * TWOD + Dc + d] = __float2bfloat16(-0.5f * v * v);
    if (b == 0 && d == 0) g_flag = 1;   // reset each launch (graph-replay safe)
}

// warp per k-row, lane handles 8 elements; writes only the m*iv half (32 MB)
__global__ void __launch_bounds__(256) prep_w_kernel(const float* __restrict__ mean,
                                                     const float* __restrict__ stddev) {
    int warp = threadIdx.x >> 5, lane = threadIdx.x & 31;
    int k = blockIdx.x * 8 + warp;
    int e = lane * 8;
    const float* mp = mean   + (size_t)k * Dc + e;
    const float* sp = stddev + (size_t)k * Dc + e;
    float4 ma = *(const float4*)mp,      mb = *(const float4*)(mp + 4);
    float4 sa = *(const float4*)sp,      sb = *(const float4*)(sp + 4);

    bool nonuni = (sa.x != 1.0f) | (sa.y != 1.0f) | (sa.z != 1.0f) | (sa.w != 1.0f) |
                  (sb.x != 1.0f) | (sb.y != 1.0f) | (sb.z != 1.0f) | (sb.w != 1.0f);
    if (nonuni) g_flag = 0;

    float m8[8] = {ma.x, ma.y, ma.z, ma.w, mb.x, mb.y, mb.z, mb.w};
    float s8[8] = {sa.x, sa.y, sa.z, sa.w, sb.x, sb.y, sb.z, sb.w};
    float part = 0.0f;
    __nv_bfloat16 w8[8];
    #pragma unroll
    for (int i = 0; i < 8; i++) {
        float iv = 1.0f / (s8[i] * s8[i]);
        float miv = m8[i] * iv;
        w8[i] = __float2bfloat16(miv);
        part = fmaf(-0.5f * m8[i], miv, part);
    }
    if (nonuni) {
        #pragma unroll
        for (int i = 0; i < 8; i++) part -= logf(s8[i]);
    }
    *(uint4*)&g_wb[(size_t)k * TWOD + e] = *(uint4*)w8;

    #pragma unroll
    for (int off = 16; off > 0; off >>= 1)
        part += __shfl_xor_sync(0xffffffffu, part, off);
    if (lane == 0) g_bias[k] = part - HALF_D_LOG2PI;
}

// fix-up: writes the iv half; runs only when some stddev != 1
__global__ void __launch_bounds__(256) prep_w_fix_kernel(const float* __restrict__ stddev) {
    if (g_flag) return;
    int warp = threadIdx.x >> 5, lane = threadIdx.x & 31;
    int k = blockIdx.x * 8 + warp;
    int e = lane * 8;
    const float* sp = stddev + (size_t)k * Dc + e;
    float4 sa = *(const float4*)sp, sb = *(const float4*)(sp + 4);
    float s8[8] = {sa.x, sa.y, sa.z, sa.w, sb.x, sb.y, sb.z, sb.w};
    __nv_bfloat16 w8[8];
    #pragma unroll
    for (int i = 0; i < 8; i++)
        w8[i] = __float2bfloat16(1.0f / (s8[i] * s8[i]));
    *(uint4*)&g_wb[(size_t)k * TWOD + Dc + e] = *(uint4*)w8;
}

// ---------------- mma.sync bf16 GEMM (+ per-tile row max) ----------------
#define NSTAGE 4
#define ROWB   80
#define STAGE_BYTES (128 * ROWB * 2)   // A + B per stage = 20480
#define GEMM_SMEM (NSTAGE * STAGE_BYTES)
#define STGROW 272                      // staging row stride (bytes)

__device__ __forceinline__ void load_stage(uint32_t sbase, int st, int m0, int n0, int k0, int tid) {
    uint32_t ab = sbase + st * STAGE_BYTES;
    uint32_t bb = ab + 128 * ROWB;
    #pragma unroll
    for (int i = 0; i < 2; i++) {
        int lin = tid + (i << 8);
        int row = lin >> 2, ch = lin & 3;
        cp_async16(ab + row * ROWB + ch * 16, g_xb + (size_t)(m0 + row) * TWOD + k0 + ch * 8);
        cp_async16(bb + row * ROWB + ch * 16, g_wb + (size_t)(n0 + row) * TWOD + k0 + ch * 8);
    }
    CP_COMMIT();
}

__global__ void __launch_bounds__(256, 2) gemm_kernel() {
    extern __shared__ char smem[];
    __shared__ float smax[128][4];
    uint32_t sbase = smem_u32(smem);
    int tid = threadIdx.x, wid = tid >> 5, lane = tid & 31;
    int m0 = blockIdx.x * 128;            // M fastest: 8 consecutive CTAs share B tile
    int n0 = blockIdx.y * 128;
    int wm = wid >> 2, wn = wid & 3;

    int uni = g_flag;
    int KT = uni ? 8 : 16;
    float SHIFTV = uni ? SHIFT_UNI : SHIFT_FULL;

    float acc[4][4][4];
    #pragma unroll
    for (int mt = 0; mt < 4; mt++)
        #pragma unroll
        for (int nt = 0; nt < 4; nt++)
            #pragma unroll
            for (int q = 0; q < 4; q++) acc[mt][nt][q] = 0.0f;

    load_stage(sbase, 0, m0, n0, 0, tid);
    load_stage(sbase, 1, m0, n0, 32, tid);
    load_stage(sbase, 2, m0, n0, 64, tid);

    uint32_t a_row = (uint32_t)(wm * 64 + (lane & 15));
    uint32_t a_off = a_row * ROWB + ((lane >> 4) << 4);
    uint32_t b_row = (uint32_t)(wn * 32 + (lane & 7) + ((lane >> 4) << 3));
    uint32_t b_off = b_row * ROWB + (((lane >> 3) & 1) << 4);

    #pragma unroll 1
    for (int it = 0; it < KT; it++) {
        CP_WAIT(2);
        __syncthreads();
        if (it + 3 < KT) load_stage(sbase, (it + 3) % NSTAGE, m0, n0, (it + 3) * 32, tid);
        else CP_COMMIT();

        int st = it % NSTAGE;
        uint32_t ab = sbase + st * STAGE_BYTES;
        uint32_t bb = ab + 128 * ROWB;

        #pragma unroll
        for (int ks = 0; ks < 2; ks++) {
            uint32_t afr[4][4];
            #pragma unroll
            for (int mt = 0; mt < 4; mt++)
                LDSM_X4(afr[mt], ab + a_off + mt * (16 * ROWB) + ks * 32);
            uint32_t bfr[2][4];
            #pragma unroll
            for (int np = 0; np < 2; np++)
                LDSM_X4(bfr[np], bb + b_off + np * (16 * ROWB) + ks * 32);
            #pragma unroll
            for (int mt = 0; mt < 4; mt++)
                #pragma unroll
                for (int nt = 0; nt < 4; nt++)
                    mma16816(acc[mt][nt], afr[mt],
                             bfr[nt >> 1][(nt & 1) * 2], bfr[nt >> 1][(nt & 1) * 2 + 1]);
        }
    }
    CP_WAIT(0);
    __syncthreads();   // all ldmatrix done: staging may overwrite pipeline smem

    const float NI = neg_inf();
    float rmA[4], rmB[4];
    #pragma unroll
    for (int mt = 0; mt < 4; mt++) { rmA[mt] = NI; rmB[mt] = NI; }

    // stage converted half2 into smem (conflict-free: 272B row stride)
    #pragma unroll
    for (int nt = 0; nt < 4; nt++) {
        int col = wn * 32 + nt * 8 + (lane & 3) * 2;
        float2 bb2 = *(const float2*)&g_bias[n0 + col];
        float bx = bb2.x + SHIFTV, by = bb2.y + SHIFTV;
        #pragma unroll
        for (int mt = 0; mt < 4; mt++) {
            int rowl = wm * 64 + mt * 16 + (lane >> 2);
            float a0 = acc[mt][nt][0] + bx, a1 = acc[mt][nt][1] + by;
            float a2 = acc[mt][nt][2] + bx, a3 = acc[mt][nt][3] + by;
            rmA[mt] = fmaxf(rmA[mt], fmaxf(a0, a1));
            rmB[mt] = fmaxf(rmB[mt], fmaxf(a2, a3));
            *(__half2*)(smem + rowl * STGROW + col * 2)       = __floats2half2_rn(a0, a1);
            *(__half2*)(smem + (rowl + 8) * STGROW + col * 2) = __floats2half2_rn(a2, a3);
        }
    }

    #pragma unroll
    for (int mt = 0; mt < 4; mt++) {
        #pragma unroll
        for (int off = 1; off < 4; off <<= 1) {
            rmA[mt] = fmaxf(rmA[mt], __shfl_xor_sync(0xffffffffu, rmA[mt], off));
            rmB[mt] = fmaxf(rmB[mt], __shfl_xor_sync(0xffffffffu, rmB[mt], off));
        }
        if ((lane & 3) == 0) {
            int lr = wm * 64 + mt * 16 + (lane >> 2);
            smax[lr][wn]     = rmA[mt];
            smax[lr + 8][wn] = rmB[mt];
        }
    }
    __syncthreads();

    // coalesced copy-out: 128 rows x 256B = 2048 uint4
    #pragma unroll
    for (int i = 0; i < 8; i++) {
        int lin = tid + (i << 8);
        int r = lin >> 4, q = lin & 15;
        uint4 v = *(const uint4*)(smem + r * STGROW + q * 16);
        *(uint4*)(g_lh + (size_t)(m0 + r) * Kc + n0 + q * 8) = v;
    }

    if (tid < 128) {
        float m = fmaxf(fmaxf(smax[tid][0], smax[tid][1]), fmaxf(smax[tid][2], smax[tid][3]));
        g_tmax[(size_t)(m0 + tid) * NTILES + blockIdx.y] = __float2half(m);
    }
}

// ---------------- topk: tile-max guided selection + exact rescore ----------------
__global__ void __launch_bounds__(512) topk_kernel(const float* __restrict__ x,
                                                   const float* __restrict__ mean,
                                                   const float* __restrict__ stddev,
                                                   const float* __restrict__ outputs,
                                                   float* __restrict__ out) {
    int b = blockIdx.x, t = threadIdx.x;
    int lane = t & 31, warp = t >> 5;
    const float NI = neg_inf();
    int uni = g_flag;

    __shared__ int   s_tiles[TCAP];
    __shared__ int   s_nt, s_cnt;
    __shared__ int   sred[16];
    __shared__ uint32_t s_cand[NCAP];
    __shared__ float s_clp[NCAP];
    __shared__ float s_fv[TOPK];
    __shared__ int   s_fi[TOPK];
    __shared__ float s_w[TOPK];
    __shared__ float part[2 * 256];

    // ---- stage 1: tile-max threshold via block-vote binary search (16-bit keys) ----
    uint32_t tk = hkey((uint32_t)__half_as_ushort(g_tmax[(size_t)b * NTILES + t]));
    uint32_t cur = 0;
    #pragma unroll 1
    for (int bit = 15; bit >= 0; --bit) {
        uint32_t T = cur | (1u << bit);
        int n = __syncthreads_count(tk >= T);
        if (n >= NCAND) cur = T;
    }
    if (t == 0) s_nt = 0;
    __syncthreads();
    if (tk >= cur) {
        int p = atomicAdd(&s_nt, 1);
        if (p < TCAP) s_tiles[p] = t;
    }
    __syncthreads();
    int ntl = s_nt < TCAP ? s_nt : TCAP;
    int total = ntl * 64;          // u32 words across selected tiles

    // ---- stage 2: gather selected tiles into registers as 16-bit keys ----
    const uint32_t* row32 = (const uint32_t*)(g_lh + (size_t)b * Kc);
    uint32_t u[16];
    #pragma unroll
    for (int i = 0; i < 16; i++) {
        int w = t + (i << 9);
        if (w < total) {
            int tile = s_tiles[w >> 6];
            u[i] = key2(row32[tile * 64 + (w & 63)]);
        } else {
            u[i] = 0x03FF03FFu;    // key of -inf in both halves
        }
    }

    // ---- stage 3: exact 16-bit threshold via block-sum binary search ----
    uint32_t cur16 = 0;
    #pragma unroll 1
    for (int bit = 15; bit >= 0; --bit) {
        uint32_t T = cur16 | (1u << bit);
        int c = 0;
        #pragma unroll
        for (int i = 0; i < 16; i++)
            c += ((u[i] & 0xFFFFu) >= T) + ((u[i] >> 16) >= T);
        #pragma unroll
        for (int off = 16; off > 0; off >>= 1)
            c += __shfl_xor_sync(0xffffffffu, c, off);
        __syncthreads();
        if (lane == 0) sred[warp] = c;
        __syncthreads();
        int n = 0;
        #pragma unroll
        for (int w = 0; w < 16; w++) n += sred[w];
        if (n >= NCAND) cur16 = T;
    }
    if (t == 0) s_cnt = 0;
    if (t < NCAP) s_clp[t] = NI;
    __syncthreads();

    // ---- stage 4: collect candidates ----
    #pragma unroll
    for (int i = 0; i < 16; i++) {
        int w = t + (i << 9);
        if (w < total) {
            uint32_t klo = u[i] & 0xFFFFu, khi = u[i] >> 16;
            uint32_t idx = (uint32_t)(s_tiles[w >> 6] * 128 + (w & 63) * 2);
            if (klo >= cur16) {
                int p = atomicAdd(&s_cnt, 1);
                if (p < NCAP) s_cand[p] = (klo << 16) | idx;
            }
            if (khi >= cur16) {
                int p = atomicAdd(&s_cnt, 1);
                if (p < NCAP) s_cand[p] = (khi << 16) | (idx + 1);
            }
        }
    }
    __syncthreads();
    int M = s_cnt < NCAP ? s_cnt : NCAP;

    // ---- exact fp32 rescore (one warp per candidate) ----
    for (int cc = warp; cc < M; cc += 16) {
        int c = (int)(s_cand[cc] & 0xFFFFu);
        float sq = 0.0f, sl = 0.0f;
        if (uni) {
            #pragma unroll
            for (int jj = 0; jj < 8; jj++) {
                int d = lane + (jj << 5);
                float m  = mean[(size_t)c * Dc + d];
                float xv = x[(size_t)b * Dc + d];
                float df = xv - m;
                sq = fmaf(df, df, sq);
            }
        } else {
            #pragma unroll
            for (int jj = 0; jj < 8; jj++) {
                int d = lane + (jj << 5);
                float m  = mean[(size_t)c * Dc + d];
                float sd = stddev[(size_t)c * Dc + d];
                float xv = x[(size_t)b * Dc + d];
                float iv = 1.0f / (sd * sd);
                float df = xv - m;
                sq = fmaf(df * df, iv, sq);
                sl += logf(sd);
            }
        }
        #pragma unroll
        for (int off = 16; off > 0; off >>= 1) {
            sq += __shfl_xor_sync(0xffffffffu, sq, off);
            sl += __shfl_xor_sync(0xffffffffu, sl, off);
        }
        if (lane == 0) s_clp[cc] = -0.5f * sq - sl - HALF_D_LOG2PI;
    }
    __syncthreads();

    // ---- exact top-32 of up to 96 rescored values (warp 0, 3 slots/lane) ----
    if (warp == 0) {
        float va[3]; int ia[3];
        #pragma unroll
        for (int q = 0; q < 3; q++) { ia[q] = lane + q * 32; va[q] = s_clp[ia[q]]; }
        for (int r = 0; r < TOPK; r++) {
            float m = va[0]; int mi = ia[0];
            if (va[1] > m) { m = va[1]; mi = ia[1]; }
            if (va[2] > m) { m = va[2]; mi = ia[2]; }
            float bm = m; int bi = mi;
            #pragma unroll
            for (int off = 16; off > 0; off >>= 1) {
                float ov = __shfl_down_sync(0xffffffffu, bm, off);
                int   oi = __shfl_down_sync(0xffffffffu, bi, off);
                if (ov > bm) { bm = ov; bi = oi; }
            }
            bm = __shfl_sync(0xffffffffu, bm, 0);
            bi = __shfl_sync(0xffffffffu, bi, 0);
            if (lane == 0) { s_fv[r] = bm; s_fi[r] = (int)(s_cand[bi] & 0xFFFFu); }
            #pragma unroll
            for (int q = 0; q < 3; q++) if (ia[q] == bi) va[q] = NI;
        }
    }
    __syncthreads();

    if (t < TOPK) {
        float e = expf(s_fv[t] - s_fv[0]);
        float s = e;
        #pragma unroll
        for (int off = 16; off > 0; off >>= 1)
            s += __shfl_xor_sync(0xffffffffu, s, off);
        s_w[t] = e / s;
    }
    __syncthreads();

    int o = t & 255, g = t >> 8;   // g in {0,1}
    float p = 0.0f;
    #pragma unroll
    for (int j = 0; j < 16; j++) {
        int jj = g * 16 + j;
        p = fmaf(s_w[jj], outputs[(size_t)s_fi[jj] * Oc + o], p);
    }
    part[g * 256 + o] = p;
    __syncthreads();
    if (t < 256)
        out[(size_t)b * Oc + t] = part[t] + part[256 + t];
}

// ---------------- launch ----------------
extern "C" void kernel_launch(void* const* d_in, const int* in_sizes, int n_in,
                              void* d_out, int out_size) {
    const float* x       = (const float*)d_in[0];
    const float* mean    = (const float*)d_in[1];
    const float* stddev  = (const float*)d_in[2];
    const float* outputs = (const float*)d_in[3];
    float* out = (float*)d_out;

    cudaFuncSetAttribute(gemm_kernel, cudaFuncAttributeMaxDynamicSharedMemorySize, GEMM_SMEM);

    prep_x_kernel<<<Bc, Dc>>>(x);
    prep_w_kernel<<<Kc / 8, 256>>>(mean, stddev);
    prep_w_fix_kernel<<<Kc / 8, 256>>>(stddev);
    gemm_kernel<<<dim3(Bc / 128, Kc / 128), 256, GEMM_SMEM>>>();
    topk_kernel<<<Bc, 512>>>(x, mean, stddev, outputs, out);
}

// round 13
// speedup vs baseline: 1.2649x; 1.0200x over previous
#include <cuda_runtime.h>
#include <cuda_bf16.h>
#include <cuda_fp16.h>
#include <math.h>
#include <stdint.h>

#define Kc 65536
#define Dc 256
#define Oc 256
#define Bc 1024
#define TOPK 32
#define NCAND 48
#define NCAP 96
#define NTILES 512
#define TCAP 128
#define TWOD 512
#define SHIFT_FULL 491.25f
#define SHIFT_UNI  363.25f
#define HALF_D_LOG2PI 235.2482645f   // 0.5 * 256 * ln(2*pi)

// ---------------- device scratch ----------------
__device__ __nv_bfloat16 g_xb[(size_t)Bc * TWOD];        // 1 MB  [x | -0.5x^2]
__device__ __nv_bfloat16 g_wb[(size_t)Kc * TWOD];        // 64 MB [m*iv | iv]
__device__ float         g_bias[Kc];
__device__ __half        g_lh[(size_t)Bc * Kc];          // 128 MB shifted logits
__device__ __half        g_tmax[(size_t)Bc * NTILES];    // 1 MB per-row per-tile max (fp16)
__device__ int           g_flag;                          // 1 => stddev == 1 everywhere

__device__ __forceinline__ float neg_inf() { return __int_as_float(0xff800000); }

__device__ __forceinline__ uint32_t smem_u32(const void* p) {
    uint32_t a;
    asm("{ .reg .u64 t; cvta.to.shared.u64 t, %1; cvt.u32.u64 %0, t; }" : "=r"(a) : "l"(p));
    return a;
}
__device__ __forceinline__ void cp_async16(uint32_t dst, const void* src) {
    asm volatile("cp.async.cg.shared.global [%0], [%1], 16;" :: "r"(dst), "l"(src));
}
#define CP_COMMIT() asm volatile("cp.async.commit_group;" ::: "memory")
#define CP_WAIT(n)  asm volatile("cp.async.wait_group %0;" :: "n"(n) : "memory")

#define LDSM_X4(r, addr) \
    asm volatile("ldmatrix.sync.aligned.m8n8.x4.shared.b16 {%0,%1,%2,%3}, [%4];" \
        : "=r"((r)[0]), "=r"((r)[1]), "=r"((r)[2]), "=r"((r)[3]) : "r"(addr))

__device__ __forceinline__ void mma16816(float* c, const uint32_t* a, uint32_t b0, uint32_t b1) {
    asm volatile("mma.sync.aligned.m16n8k16.row.col.f32.bf16.bf16.f32 "
        "{%0,%1,%2,%3}, {%4,%5,%6,%7}, {%8,%9}, {%0,%1,%2,%3};"
        : "+f"(c[0]), "+f"(c[1]), "+f"(c[2]), "+f"(c[3])
        : "r"(a[0]), "r"(a[1]), "r"(a[2]), "r"(a[3]), "r"(b0), "r"(b1));
}

// both halves of a half2 word -> order-preserving 16-bit keys
__device__ __forceinline__ uint32_t key2(uint32_t h2) {
    uint32_t s = h2 & 0x80008000u;
    uint32_t m = 0x80008000u | ((s >> 15) * 0x7FFFu);
    return h2 ^ m;
}
__device__ __forceinline__ uint32_t hkey(uint32_t h) {   // single fp16 bits -> 16-bit key
    return h ^ ((h & 0x8000u) ? 0xFFFFu : 0x8000u);
}

// ---------------- prep kernels ----------------
__global__ void prep_x_kernel(const float* __restrict__ x) {
    int b = blockIdx.x, d = threadIdx.x;
    float v = x[b * Dc + d];
    g_xb[(size_t)b * TWOD + d]      = __float2bfloat16(v);
    g_xb[(size_t)b * TWOD + Dc + d] = __float2bfloat16(-0.5f * v * v);
    if (b == 0 && d == 0) g_flag = 1;   // reset each launch (graph-replay safe)
}

// warp per k-row, lane handles 8 elements; writes only the m*iv half (32 MB)
__global__ void __launch_bounds__(256) prep_w_kernel(const float* __restrict__ mean,
                                                     const float* __restrict__ stddev) {
    int warp = threadIdx.x >> 5, lane = threadIdx.x & 31;
    int k = blockIdx.x * 8 + warp;
    int e = lane * 8;
    const float* mp = mean   + (size_t)k * Dc + e;
    const float* sp = stddev + (size_t)k * Dc + e;
    float4 ma = *(const float4*)mp,      mb = *(const float4*)(mp + 4);
    float4 sa = *(const float4*)sp,      sb = *(const float4*)(sp + 4);

    bool nonuni = (sa.x != 1.0f) | (sa.y != 1.0f) | (sa.z != 1.0f) | (sa.w != 1.0f) |
                  (sb.x != 1.0f) | (sb.y != 1.0f) | (sb.z != 1.0f) | (sb.w != 1.0f);
    if (nonuni) g_flag = 0;

    float m8[8] = {ma.x, ma.y, ma.z, ma.w, mb.x, mb.y, mb.z, mb.w};
    float s8[8] = {sa.x, sa.y, sa.z, sa.w, sb.x, sb.y, sb.z, sb.w};
    float part = 0.0f;
    __nv_bfloat16 w8[8];
    #pragma unroll
    for (int i = 0; i < 8; i++) {
        float iv = 1.0f / (s8[i] * s8[i]);
        float miv = m8[i] * iv;
        w8[i] = __float2bfloat16(miv);
        part = fmaf(-0.5f * m8[i], miv, part);
    }
    if (nonuni) {
        #pragma unroll
        for (int i = 0; i < 8; i++) part -= logf(s8[i]);
    }
    *(uint4*)&g_wb[(size_t)k * TWOD + e] = *(uint4*)w8;

    #pragma unroll
    for (int off = 16; off > 0; off >>= 1)
        part += __shfl_xor_sync(0xffffffffu, part, off);
    if (lane == 0) g_bias[k] = part - HALF_D_LOG2PI;
}

// fix-up: writes the iv half; runs only when some stddev != 1
__global__ void __launch_bounds__(256) prep_w_fix_kernel(const float* __restrict__ stddev) {
    if (g_flag) return;
    int warp = threadIdx.x >> 5, lane = threadIdx.x & 31;
    int k = blockIdx.x * 8 + warp;
    int e = lane * 8;
    const float* sp = stddev + (size_t)k * Dc + e;
    float4 sa = *(const float4*)sp, sb = *(const float4*)(sp + 4);
    float s8[8] = {sa.x, sa.y, sa.z, sa.w, sb.x, sb.y, sb.z, sb.w};
    __nv_bfloat16 w8[8];
    #pragma unroll
    for (int i = 0; i < 8; i++)
        w8[i] = __float2bfloat16(1.0f / (s8[i] * s8[i]));
    *(uint4*)&g_wb[(size_t)k * TWOD + Dc + e] = *(uint4*)w8;
}

// ---------------- mma.sync bf16 GEMM (+ per-tile row max) ----------------
// 128x128 CTA tile, 4 warps (2x2), 64x64 warp tiles: halves LDSM redundancy.
#define NSTAGE 4
#define ROWB   80
#define STAGE_BYTES (128 * ROWB * 2)   // A + B per stage = 20480
#define GEMM_SMEM (NSTAGE * STAGE_BYTES)
#define STGROW 272                      // staging row stride (bytes)

__device__ __forceinline__ void load_stage(uint32_t sbase, int st, int m0, int n0, int k0, int tid) {
    uint32_t ab = sbase + st * STAGE_BYTES;
    uint32_t bb = ab + 128 * ROWB;
    #pragma unroll
    for (int i = 0; i < 4; i++) {
        int lin = tid + (i << 7);
        int row = lin >> 2, ch = lin & 3;
        cp_async16(ab + row * ROWB + ch * 16, g_xb + (size_t)(m0 + row) * TWOD + k0 + ch * 8);
        cp_async16(bb + row * ROWB + ch * 16, g_wb + (size_t)(n0 + row) * TWOD + k0 + ch * 8);
    }
    CP_COMMIT();
}

__global__ void __launch_bounds__(128, 2) gemm_kernel() {
    extern __shared__ char smem[];
    __shared__ float smax[128][2];
    uint32_t sbase = smem_u32(smem);
    int tid = threadIdx.x, wid = tid >> 5, lane = tid & 31;
    int m0 = blockIdx.x * 128;            // M fastest: consecutive CTAs share B tile
    int n0 = blockIdx.y * 128;
    int wm = wid >> 1, wn = wid & 1;

    int uni = g_flag;
    int KT = uni ? 8 : 16;
    float SHIFTV = uni ? SHIFT_UNI : SHIFT_FULL;

    float acc[4][8][4];
    #pragma unroll
    for (int mt = 0; mt < 4; mt++)
        #pragma unroll
        for (int nt = 0; nt < 8; nt++)
            #pragma unroll
            for (int q = 0; q < 4; q++) acc[mt][nt][q] = 0.0f;

    load_stage(sbase, 0, m0, n0, 0, tid);
    load_stage(sbase, 1, m0, n0, 32, tid);
    load_stage(sbase, 2, m0, n0, 64, tid);

    uint32_t a_row = (uint32_t)(wm * 64 + (lane & 15));
    uint32_t a_off = a_row * ROWB + ((lane >> 4) << 4);
    uint32_t b_row = (uint32_t)(wn * 64 + (lane & 7) + ((lane >> 4) << 3));
    uint32_t b_off = b_row * ROWB + (((lane >> 3) & 1) << 4);

    #pragma unroll 1
    for (int it = 0; it < KT; it++) {
        CP_WAIT(2);
        __syncthreads();
        if (it + 3 < KT) load_stage(sbase, (it + 3) % NSTAGE, m0, n0, (it + 3) * 32, tid);
        else CP_COMMIT();

        int st = it % NSTAGE;
        uint32_t ab = sbase + st * STAGE_BYTES;
        uint32_t bb = ab + 128 * ROWB;

        #pragma unroll
        for (int ks = 0; ks < 2; ks++) {
            uint32_t afr[4][4];
            #pragma unroll
            for (int mt = 0; mt < 4; mt++)
                LDSM_X4(afr[mt], ab + a_off + mt * (16 * ROWB) + ks * 32);
            uint32_t bfr[4][4];
            #pragma unroll
            for (int np = 0; np < 4; np++)
                LDSM_X4(bfr[np], bb + b_off + np * (16 * ROWB) + ks * 32);
            #pragma unroll
            for (int mt = 0; mt < 4; mt++)
                #pragma unroll
                for (int nt = 0; nt < 8; nt++)
                    mma16816(acc[mt][nt], afr[mt],
                             bfr[nt >> 1][(nt & 1) * 2], bfr[nt >> 1][(nt & 1) * 2 + 1]);
        }
    }
    CP_WAIT(0);
    __syncthreads();   // all ldmatrix done: staging may overwrite pipeline smem

    const float NI = neg_inf();
    float rmA[4], rmB[4];
    #pragma unroll
    for (int mt = 0; mt < 4; mt++) { rmA[mt] = NI; rmB[mt] = NI; }

    // stage converted half2 into smem (conflict-free: 272B row stride)
    #pragma unroll
    for (int nt = 0; nt < 8; nt++) {
        int col = wn * 64 + nt * 8 + (lane & 3) * 2;
        float2 bb2 = *(const float2*)&g_bias[n0 + col];
        float bx = bb2.x + SHIFTV, by = bb2.y + SHIFTV;
        #pragma unroll
        for (int mt = 0; mt < 4; mt++) {
            int rowl = wm * 64 + mt * 16 + (lane >> 2);
            float a0 = acc[mt][nt][0] + bx, a1 = acc[mt][nt][1] + by;
            float a2 = acc[mt][nt][2] + bx, a3 = acc[mt][nt][3] + by;
            rmA[mt] = fmaxf(rmA[mt], fmaxf(a0, a1));
            rmB[mt] = fmaxf(rmB[mt], fmaxf(a2, a3));
            *(__half2*)(smem + rowl * STGROW + col * 2)       = __floats2half2_rn(a0, a1);
            *(__half2*)(smem + (rowl + 8) * STGROW + col * 2) = __floats2half2_rn(a2, a3);
        }
    }

    #pragma unroll
    for (int mt = 0; mt < 4; mt++) {
        #pragma unroll
        for (int off = 1; off < 4; off <<= 1) {
            rmA[mt] = fmaxf(rmA[mt], __shfl_xor_sync(0xffffffffu, rmA[mt], off));
            rmB[mt] = fmaxf(rmB[mt], __shfl_xor_sync(0xffffffffu, rmB[mt], off));
        }
        if ((lane & 3) == 0) {
            int lr = wm * 64 + mt * 16 + (lane >> 2);
            smax[lr][wn]     = rmA[mt];
            smax[lr + 8][wn] = rmB[mt];
        }
    }
    __syncthreads();

    // coalesced copy-out: 128 rows x 256B = 2048 uint4, 16 per thread
    #pragma unroll
    for (int i = 0; i < 16; i++) {
        int lin = tid + (i << 7);
        int r = lin >> 4, q = lin & 15;
        uint4 v = *(const uint4*)(smem + r * STGROW + q * 16);
        *(uint4*)(g_lh + (size_t)(m0 + r) * Kc + n0 + q * 8) = v;
    }

    {
        float m = fmaxf(smax[tid][0], smax[tid][1]);
        g_tmax[(size_t)(m0 + tid) * NTILES + blockIdx.y] = __float2half(m);
    }
}

// ---------------- topk: tile-max guided selection + exact rescore ----------------
__global__ void __launch_bounds__(512) topk_kernel(const float* __restrict__ x,
                                                   const float* __restrict__ mean,
                                                   const float* __restrict__ stddev,
                                                   const float* __restrict__ outputs,
                                                   float* __restrict__ out) {
    int b = blockIdx.x, t = threadIdx.x;
    int lane = t & 31, warp = t >> 5;
    const float NI = neg_inf();
    int uni = g_flag;

    __shared__ int   s_tiles[TCAP];
    __shared__ int   s_nt, s_cnt;
    __shared__ int   sred[16];
    __shared__ uint32_t s_cand[NCAP];
    __shared__ float s_clp[NCAP];
    __shared__ float s_fv[TOPK];
    __shared__ int   s_fi[TOPK];
    __shared__ float s_w[TOPK];
    __shared__ float part[2 * 256];

    // ---- stage 1: tile-max threshold via block-vote binary search (16-bit keys) ----
    uint32_t tk = hkey((uint32_t)__half_as_ushort(g_tmax[(size_t)b * NTILES + t]));
    uint32_t cur = 0;
    #pragma unroll 1
    for (int bit = 15; bit >= 0; --bit) {
        uint32_t T = cur | (1u << bit);
        int n = __syncthreads_count(tk >= T);
        if (n >= NCAND) cur = T;
    }
    if (t == 0) s_nt = 0;
    __syncthreads();
    if (tk >= cur) {
        int p = atomicAdd(&s_nt, 1);
        if (p < TCAP) s_tiles[p] = t;
    }
    __syncthreads();
    int ntl = s_nt < TCAP ? s_nt : TCAP;
    int total = ntl * 64;          // u32 words across selected tiles

    // ---- stage 2: gather selected tiles into registers as 16-bit keys ----
    const uint32_t* row32 = (const uint32_t*)(g_lh + (size_t)b * Kc);
    uint32_t u[16];
    #pragma unroll
    for (int i = 0; i < 16; i++) {
        int w = t + (i << 9);
        if (w < total) {
            int tile = s_tiles[w >> 6];
            u[i] = key2(row32[tile * 64 + (w & 63)]);
        } else {
            u[i] = 0x03FF03FFu;    // key of -inf in both halves
        }
    }

    // ---- stage 3: exact 16-bit threshold via block-sum binary search ----
    uint32_t cur16 = 0;
    #pragma unroll 1
    for (int bit = 15; bit >= 0; --bit) {
        uint32_t T = cur16 | (1u << bit);
        int c = 0;
        #pragma unroll
        for (int i = 0; i < 16; i++)
            c += ((u[i] & 0xFFFFu) >= T) + ((u[i] >> 16) >= T);
        #pragma unroll
        for (int off = 16; off > 0; off >>= 1)
            c += __shfl_xor_sync(0xffffffffu, c, off);
        __syncthreads();
        if (lane == 0) sred[warp] = c;
        __syncthreads();
        int n = 0;
        #pragma unroll
        for (int w = 0; w < 16; w++) n += sred[w];
        if (n >= NCAND) cur16 = T;
    }
    if (t == 0) s_cnt = 0;
    if (t < NCAP) s_clp[t] = NI;
    __syncthreads();

    // ---- stage 4: collect candidates ----
    #pragma unroll
    for (int i = 0; i < 16; i++) {
        int w = t + (i << 9);
        if (w < total) {
            uint32_t klo = u[i] & 0xFFFFu, khi = u[i] >> 16;
            uint32_t idx = (uint32_t)(s_tiles[w >> 6] * 128 + (w & 63) * 2);
            if (klo >= cur16) {
                int p = atomicAdd(&s_cnt, 1);
                if (p < NCAP) s_cand[p] = (klo << 16) | idx;
            }
            if (khi >= cur16) {
                int p = atomicAdd(&s_cnt, 1);
                if (p < NCAP) s_cand[p] = (khi << 16) | (idx + 1);
            }
        }
    }
    __syncthreads();
    int M = s_cnt < NCAP ? s_cnt : NCAP;

    // ---- exact fp32 rescore (one warp per candidate) ----
    for (int cc = warp; cc < M; cc += 16) {
        int c = (int)(s_cand[cc] & 0xFFFFu);
        float sq = 0.0f, sl = 0.0f;
        if (uni) {
            #pragma unroll
            for (int jj = 0; jj < 8; jj++) {
                int d = lane + (jj << 5);
                float m  = mean[(size_t)c * Dc + d];
                float xv = x[(size_t)b * Dc + d];
                float df = xv - m;
                sq = fmaf(df, df, sq);
            }
        } else {
            #pragma unroll
            for (int jj = 0; jj < 8; jj++) {
                int d = lane + (jj << 5);
                float m  = mean[(size_t)c * Dc + d];
                float sd = stddev[(size_t)c * Dc + d];
                float xv = x[(size_t)b * Dc + d];
                float iv = 1.0f / (sd * sd);
                float df = xv - m;
                sq = fmaf(df * df, iv, sq);
                sl += logf(sd);
            }
        }
        #pragma unroll
        for (int off = 16; off > 0; off >>= 1) {
            sq += __shfl_xor_sync(0xffffffffu, sq, off);
            sl += __shfl_xor_sync(0xffffffffu, sl, off);
        }
        if (lane == 0) s_clp[cc] = -0.5f * sq - sl - HALF_D_LOG2PI;
    }
    __syncthreads();

    // ---- exact top-32 of up to 96 rescored values (warp 0, 3 slots/lane) ----
    if (warp == 0) {
        float va[3]; int ia[3];
        #pragma unroll
        for (int q = 0; q < 3; q++) { ia[q] = lane + q * 32; va[q] = s_clp[ia[q]]; }
        for (int r = 0; r < TOPK; r++) {
            float m = va[0]; int mi = ia[0];
            if (va[1] > m) { m = va[1]; mi = ia[1]; }
            if (va[2] > m) { m = va[2]; mi = ia[2]; }
            float bm = m; int bi = mi;
            #pragma unroll
            for (int off = 16; off > 0; off >>= 1) {
                float ov = __shfl_down_sync(0xffffffffu, bm, off);
                int   oi = __shfl_down_sync(0xffffffffu, bi, off);
                if (ov > bm) { bm = ov; bi = oi; }
            }
            bm = __shfl_sync(0xffffffffu, bm, 0);
            bi = __shfl_sync(0xffffffffu, bi, 0);
            if (lane == 0) { s_fv[r] = bm; s_fi[r] = (int)(s_cand[bi] & 0xFFFFu); }
            #pragma unroll
            for (int q = 0; q < 3; q++) if (ia[q] == bi) va[q] = NI;
        }
    }
    __syncthreads();

    if (t < TOPK) {
        float e = expf(s_fv[t] - s_fv[0]);
        float s = e;
        #pragma unroll
        for (int off = 16; off > 0; off >>= 1)
            s += __shfl_xor_sync(0xffffffffu, s, off);
        s_w[t] = e / s;
    }
    __syncthreads();

    int o = t & 255, g = t >> 8;   // g in {0,1}
    float p = 0.0f;
    #pragma unroll
    for (int j = 0; j < 16; j++) {
        int jj = g * 16 + j;
        p = fmaf(s_w[jj], outputs[(size_t)s_fi[jj] * Oc + o], p);
    }
    part[g * 256 + o] = p;
    __syncthreads();
    if (t < 256)
        out[(size_t)b * Oc + t] = part[t] + part[256 + t];
}

// ---------------- launch ----------------
extern "C" void kernel_launch(void* const* d_in, const int* in_sizes, int n_in,
                              void* d_out, int out_size) {
    const float* x       = (const float*)d_in[0];
    const float* mean    = (const float*)d_in[1];
    const float* stddev  = (const float*)d_in[2];
    const float* outputs = (const float*)d_in[3];
    float* out = (float*)d_out;

    cudaFuncSetAttribute(gemm_kernel, cudaFuncAttributeMaxDynamicSharedMemorySize, GEMM_SMEM);

    prep_x_kernel<<<Bc, Dc>>>(x);
    prep_w_kernel<<<Kc / 8, 256>>>(mean, stddev);
    prep_w_fix_kernel<<<Kc / 8, 256>>>(stddev);
    gemm_kernel<<<dim3(Bc / 128, Kc / 128), 128, GEMM_SMEM>>>();
    topk_kernel<<<Bc, 512>>>(x, mean, stddev, outputs, out);
}

// round 14
// speedup vs baseline: 1.4274x; 1.1285x over previous
#include <cuda_runtime.h>
#include <cuda_bf16.h>
#include <cuda_fp16.h>
#include <math.h>
#include <stdint.h>

#define Kc 65536
#define Dc 256
#define Oc 256
#define Bc 1024
#define TOPK 32
#define NCAND 48
#define NCAP 128
#define NTILES 512
#define TCAP 128
#define TWOD 512
#define SHIFT_FULL 491.25f
#define SHIFT_UNI  363.25f
#define HALF_D_LOG2PI 235.2482645f   // 0.5 * 256 * ln(2*pi)

// ---------------- device scratch ----------------
__device__ __nv_bfloat16 g_xb[(size_t)Bc * TWOD];        // 1 MB  [x | -0.5x^2]
__device__ __nv_bfloat16 g_wb[(size_t)Kc * TWOD];        // 64 MB [m*iv | iv]
__device__ float         g_bias[Kc];
__device__ __half        g_lh[(size_t)Bc * Kc];          // 128 MB shifted logits
__device__ __half        g_tmax[(size_t)Bc * NTILES];    // 1 MB per-row per-tile max (fp16)
__device__ int           g_flag;                          // 1 => stddev == 1 everywhere

__device__ __forceinline__ float neg_inf() { return __int_as_float(0xff800000); }

__device__ __forceinline__ uint32_t smem_u32(const void* p) {
    uint32_t a;
    asm("{ .reg .u64 t; cvta.to.shared.u64 t, %1; cvt.u32.u64 %0, t; }" : "=r"(a) : "l"(p));
    return a;
}
__device__ __forceinline__ void cp_async16(uint32_t dst, const void* src) {
    asm volatile("cp.async.cg.shared.global [%0], [%1], 16;" :: "r"(dst), "l"(src));
}
#define CP_COMMIT() asm volatile("cp.async.commit_group;" ::: "memory")
#define CP_WAIT(n)  asm volatile("cp.async.wait_group %0;" :: "n"(n) : "memory")

#define LDSM_X4(r, addr) \
    asm volatile("ldmatrix.sync.aligned.m8n8.x4.shared.b16 {%0,%1,%2,%3}, [%4];" \
        : "=r"((r)[0]), "=r"((r)[1]), "=r"((r)[2]), "=r"((r)[3]) : "r"(addr))

__device__ __forceinline__ void mma16816(float* c, const uint32_t* a, uint32_t b0, uint32_t b1) {
    asm volatile("mma.sync.aligned.m16n8k16.row.col.f32.bf16.bf16.f32 "
        "{%0,%1,%2,%3}, {%4,%5,%6,%7}, {%8,%9}, {%0,%1,%2,%3};"
        : "+f"(c[0]), "+f"(c[1]), "+f"(c[2]), "+f"(c[3])
        : "r"(a[0]), "r"(a[1]), "r"(a[2]), "r"(a[3]), "r"(b0), "r"(b1));
}

// both halves of a half2 word -> order-preserving 16-bit keys
__device__ __forceinline__ uint32_t key2(uint32_t h2) {
    uint32_t s = h2 & 0x80008000u;
    uint32_t m = 0x80008000u | ((s >> 15) * 0x7FFFu);
    return h2 ^ m;
}
__device__ __forceinline__ uint32_t hkey(uint32_t h) {   // single fp16 bits -> 16-bit key
    return h ^ ((h & 0x8000u) ? 0xFFFFu : 0x8000u);
}

// ---------------- prep kernels ----------------
__global__ void prep_x_kernel(const float* __restrict__ x) {
    int b = blockIdx.x, d = threadIdx.x;
    float v = x[b * Dc + d];
    g_xb[(size_t)b * TWOD + d]      = __float2bfloat16(v);
    g_xb[(size_t)b * TWOD + Dc + d] = __float2bfloat16(-0.5f * v * v);
    if (b == 0 && d == 0) g_flag = 1;   // reset each launch (graph-replay safe)
}

// warp per k-row, lane handles 8 elements; writes only the m*iv half (32 MB)
__global__ void __launch_bounds__(256) prep_w_kernel(const float* __restrict__ mean,
                                                     const float* __restrict__ stddev) {
    int warp = threadIdx.x >> 5, lane = threadIdx.x & 31;
    int k = blockIdx.x * 8 + warp;
    int e = lane * 8;
    const float* mp = mean   + (size_t)k * Dc + e;
    const float* sp = stddev + (size_t)k * Dc + e;
    float4 ma = *(const float4*)mp,      mb = *(const float4*)(mp + 4);
    float4 sa = *(const float4*)sp,      sb = *(const float4*)(sp + 4);

    bool nonuni = (sa.x != 1.0f) | (sa.y != 1.0f) | (sa.z != 1.0f) | (sa.w != 1.0f) |
                  (sb.x != 1.0f) | (sb.y != 1.0f) | (sb.z != 1.0f) | (sb.w != 1.0f);
    if (nonuni) g_flag = 0;

    float m8[8] = {ma.x, ma.y, ma.z, ma.w, mb.x, mb.y, mb.z, mb.w};
    float s8[8] = {sa.x, sa.y, sa.z, sa.w, sb.x, sb.y, sb.z, sb.w};
    float part = 0.0f;
    __nv_bfloat16 w8[8];
    #pragma unroll
    for (int i = 0; i < 8; i++) {
        float iv = 1.0f / (s8[i] * s8[i]);
        float miv = m8[i] * iv;
        w8[i] = __float2bfloat16(miv);
        part = fmaf(-0.5f * m8[i], miv, part);
    }
    if (nonuni) {
        #pragma unroll
        for (int i = 0; i < 8; i++) part -= logf(s8[i]);
    }
    *(uint4*)&g_wb[(size_t)k * TWOD + e] = *(uint4*)w8;

    #pragma unroll
    for (int off = 16; off > 0; off >>= 1)
        part += __shfl_xor_sync(0xffffffffu, part, off);
    if (lane == 0) g_bias[k] = part - HALF_D_LOG2PI;
}

// fix-up: writes the iv half; runs only when some stddev != 1
__global__ void __launch_bounds__(256) prep_w_fix_kernel(const float* __restrict__ stddev) {
    if (g_flag) return;
    int warp = threadIdx.x >> 5, lane = threadIdx.x & 31;
    int k = blockIdx.x * 8 + warp;
    int e = lane * 8;
    const float* sp = stddev + (size_t)k * Dc + e;
    float4 sa = *(const float4*)sp, sb = *(const float4*)(sp + 4);
    float s8[8] = {sa.x, sa.y, sa.z, sa.w, sb.x, sb.y, sb.z, sb.w};
    __nv_bfloat16 w8[8];
    #pragma unroll
    for (int i = 0; i < 8; i++)
        w8[i] = __float2bfloat16(1.0f / (s8[i] * s8[i]));
    *(uint4*)&g_wb[(size_t)k * TWOD + Dc + e] = *(uint4*)w8;
}

// ---------------- mma.sync bf16 GEMM (+ per-tile row max) ----------------
// 128x128 CTA tile, 4 warps (2x2), 64x64 warp tiles.
#define NSTAGE 4
#define ROWB   80
#define STAGE_BYTES (128 * ROWB * 2)   // A + B per stage = 20480
#define GEMM_SMEM (NSTAGE * STAGE_BYTES)
#define STGROW 272                      // staging row stride (bytes)

__device__ __forceinline__ void load_stage(uint32_t sbase, int st, int m0, int n0, int k0, int tid) {
    uint32_t ab = sbase + st * STAGE_BYTES;
    uint32_t bb = ab + 128 * ROWB;
    #pragma unroll
    for (int i = 0; i < 4; i++) {
        int lin = tid + (i << 7);
        int row = lin >> 2, ch = lin & 3;
        cp_async16(ab + row * ROWB + ch * 16, g_xb + (size_t)(m0 + row) * TWOD + k0 + ch * 8);
        cp_async16(bb + row * ROWB + ch * 16, g_wb + (size_t)(n0 + row) * TWOD + k0 + ch * 8);
    }
    CP_COMMIT();
}

__global__ void __launch_bounds__(128, 2) gemm_kernel() {
    extern __shared__ char smem[];
    __shared__ float smax[128][2];
    uint32_t sbase = smem_u32(smem);
    int tid = threadIdx.x, wid = tid >> 5, lane = tid & 31;
    int m0 = blockIdx.x * 128;            // M fastest: consecutive CTAs share B tile
    int n0 = blockIdx.y * 128;
    int wm = wid >> 1, wn = wid & 1;

    int uni = g_flag;
    int KT = uni ? 8 : 16;
    float SHIFTV = uni ? SHIFT_UNI : SHIFT_FULL;

    float acc[4][8][4];
    #pragma unroll
    for (int mt = 0; mt < 4; mt++)
        #pragma unroll
        for (int nt = 0; nt < 8; nt++)
            #pragma unroll
            for (int q = 0; q < 4; q++) acc[mt][nt][q] = 0.0f;

    load_stage(sbase, 0, m0, n0, 0, tid);
    load_stage(sbase, 1, m0, n0, 32, tid);
    load_stage(sbase, 2, m0, n0, 64, tid);

    uint32_t a_row = (uint32_t)(wm * 64 + (lane & 15));
    uint32_t a_off = a_row * ROWB + ((lane >> 4) << 4);
    uint32_t b_row = (uint32_t)(wn * 64 + (lane & 7) + ((lane >> 4) << 3));
    uint32_t b_off = b_row * ROWB + (((lane >> 3) & 1) << 4);

    #pragma unroll 1
    for (int it = 0; it < KT; it++) {
        CP_WAIT(2);
        __syncthreads();
        if (it + 3 < KT) load_stage(sbase, (it + 3) % NSTAGE, m0, n0, (it + 3) * 32, tid);
        else CP_COMMIT();

        int st = it % NSTAGE;
        uint32_t ab = sbase + st * STAGE_BYTES;
        uint32_t bb = ab + 128 * ROWB;

        #pragma unroll
        for (int ks = 0; ks < 2; ks++) {
            uint32_t afr[4][4];
            #pragma unroll
            for (int mt = 0; mt < 4; mt++)
                LDSM_X4(afr[mt], ab + a_off + mt * (16 * ROWB) + ks * 32);
            uint32_t bfr[4][4];
            #pragma unroll
            for (int np = 0; np < 4; np++)
                LDSM_X4(bfr[np], bb + b_off + np * (16 * ROWB) + ks * 32);
            #pragma unroll
            for (int mt = 0; mt < 4; mt++)
                #pragma unroll
                for (int nt = 0; nt < 8; nt++)
                    mma16816(acc[mt][nt], afr[mt],
                             bfr[nt >> 1][(nt & 1) * 2], bfr[nt >> 1][(nt & 1) * 2 + 1]);
        }
    }
    CP_WAIT(0);
    __syncthreads();   // all ldmatrix done: staging may overwrite pipeline smem

    const float NI = neg_inf();
    float rmA[4], rmB[4];
    #pragma unroll
    for (int mt = 0; mt < 4; mt++) { rmA[mt] = NI; rmB[mt] = NI; }

    // stage converted half2 into smem (conflict-free: 272B row stride)
    #pragma unroll
    for (int nt = 0; nt < 8; nt++) {
        int col = wn * 64 + nt * 8 + (lane & 3) * 2;
        float2 bb2 = *(const float2*)&g_bias[n0 + col];
        float bx = bb2.x + SHIFTV, by = bb2.y + SHIFTV;
        #pragma unroll
        for (int mt = 0; mt < 4; mt++) {
            int rowl = wm * 64 + mt * 16 + (lane >> 2);
            float a0 = acc[mt][nt][0] + bx, a1 = acc[mt][nt][1] + by;
            float a2 = acc[mt][nt][2] + bx, a3 = acc[mt][nt][3] + by;
            rmA[mt] = fmaxf(rmA[mt], fmaxf(a0, a1));
            rmB[mt] = fmaxf(rmB[mt], fmaxf(a2, a3));
            *(__half2*)(smem + rowl * STGROW + col * 2)       = __floats2half2_rn(a0, a1);
            *(__half2*)(smem + (rowl + 8) * STGROW + col * 2) = __floats2half2_rn(a2, a3);
        }
    }

    #pragma unroll
    for (int mt = 0; mt < 4; mt++) {
        #pragma unroll
        for (int off = 1; off < 4; off <<= 1) {
            rmA[mt] = fmaxf(rmA[mt], __shfl_xor_sync(0xffffffffu, rmA[mt], off));
            rmB[mt] = fmaxf(rmB[mt], __shfl_xor_sync(0xffffffffu, rmB[mt], off));
        }
        if ((lane & 3) == 0) {
            int lr = wm * 64 + mt * 16 + (lane >> 2);
            smax[lr][wn]     = rmA[mt];
            smax[lr + 8][wn] = rmB[mt];
        }
    }
    __syncthreads();

    // coalesced copy-out: 128 rows x 256B = 2048 uint4, 16 per thread
    #pragma unroll
    for (int i = 0; i < 16; i++) {
        int lin = tid + (i << 7);
        int r = lin >> 4, q = lin & 15;
        uint4 v = *(const uint4*)(smem + r * STGROW + q * 16);
        *(uint4*)(g_lh + (size_t)(m0 + r) * Kc + n0 + q * 8) = v;
    }

    {
        float m = fmaxf(smax[tid][0], smax[tid][1]);
        // rn is monotonic: half(max fp32) == max over tile of half(v)
        g_tmax[(size_t)(m0 + tid) * NTILES + blockIdx.y] = __float2half(m);
    }
}

// ---------------- topk: tile-max threshold IS the value threshold ----------------
__global__ void __launch_bounds__(512) topk_kernel(const float* __restrict__ x,
                                                   const float* __restrict__ mean,
                                                   const float* __restrict__ stddev,
                                                   const float* __restrict__ outputs,
                                                   float* __restrict__ out) {
    int b = blockIdx.x, t = threadIdx.x;
    int lane = t & 31, warp = t >> 5;
    const float NI = neg_inf();
    int uni = g_flag;

    __shared__ int   s_tiles[TCAP];
    __shared__ int   s_nt, s_cnt;
    __shared__ int   sred[16];
    __shared__ uint32_t s_cand[NCAP];
    __shared__ float s_clp[NCAP];
    __shared__ float s_fv[TOPK];
    __shared__ int   s_fi[TOPK];
    __shared__ float s_w[TOPK];
    __shared__ float part[2 * 256];

    // ---- stage 1: cur = key of the NCAND-th largest tile max (16 vote rounds) ----
    uint32_t tk = hkey((uint32_t)__half_as_ushort(g_tmax[(size_t)b * NTILES + t]));
    uint32_t cur = 0;
    #pragma unroll 1
    for (int bit = 15; bit >= 0; --bit) {
        uint32_t T = cur | (1u << bit);
        int n = __syncthreads_count(tk >= T);
        if (n >= NCAND) cur = T;
    }
    if (t == 0) { s_nt = 0; s_cnt = 0; }
    __syncthreads();
    if (tk >= cur) {
        int p = atomicAdd(&s_nt, 1);
        if (p < TCAP) s_tiles[p] = t;
    }
    if (t < NCAP) s_clp[t] = NI;
    __syncthreads();
    int ntl = s_nt < TCAP ? s_nt : TCAP;
    int total = ntl * 64;          // u32 words across selected tiles

    // ---- stage 2: collect values with key >= cur directly (no second search).
    // Every top-NCAND value has key >= cur (the NCAND tiles' maxima are distinct
    // values >= cur, so the NCAND-th largest value >= cur), and all such values
    // live in the selected tiles. Expected count ~= 50 << NCAP.
    const uint32_t* row32 = (const uint32_t*)(g_lh + (size_t)b * Kc);
    #pragma unroll 4
    for (int i = 0; i < 16; i++) {
        int w = t + (i << 9);
        if (w < total) {
            int tile = s_tiles[w >> 6];
            uint32_t k2 = key2(row32[tile * 64 + (w & 63)]);
            uint32_t klo = k2 & 0xFFFFu, khi = k2 >> 16;
            uint32_t idx = (uint32_t)(tile * 128 + (w & 63) * 2);
            if (klo >= cur) {
                int p = atomicAdd(&s_cnt, 1);
                if (p < NCAP) s_cand[p] = (klo << 16) | idx;
            }
            if (khi >= cur) {
                int p = atomicAdd(&s_cnt, 1);
                if (p < NCAP) s_cand[p] = (khi << 16) | (idx + 1);
            }
        }
    }
    __syncthreads();
    int M = s_cnt;

    if (M > NCAP) {
        // ---- exact fallback (overflow; probability ~0): full 16-bit threshold search ----
        uint32_t u[16];
        #pragma unroll
        for (int i = 0; i < 16; i++) {
            int w = t + (i << 9);
            u[i] = (w < total) ? key2(row32[s_tiles[w >> 6] * 64 + (w & 63)]) : 0x03FF03FFu;
        }
        uint32_t cur16 = 0;
        #pragma unroll 1
        for (int bit = 15; bit >= 0; --bit) {
            uint32_t T = cur16 | (1u << bit);
            int c = 0;
            #pragma unroll
            for (int i = 0; i < 16; i++)
                c += ((u[i] & 0xFFFFu) >= T) + ((u[i] >> 16) >= T);
            #pragma unroll
            for (int off = 16; off > 0; off >>= 1)
                c += __shfl_xor_sync(0xffffffffu, c, off);
            __syncthreads();
            if (lane == 0) sred[warp] = c;
            __syncthreads();
            int n = 0;
            #pragma unroll
            for (int w2 = 0; w2 < 16; w2++) n += sred[w2];
            if (n >= NCAND) cur16 = T;
        }
        if (t == 0) s_cnt = 0;
        __syncthreads();
        #pragma unroll
        for (int i = 0; i < 16; i++) {
            int w = t + (i << 9);
            if (w < total) {
                uint32_t klo = u[i] & 0xFFFFu, khi = u[i] >> 16;
                uint32_t idx = (uint32_t)(s_tiles[w >> 6] * 128 + (w & 63) * 2);
                if (klo >= cur16) {
                    int p = atomicAdd(&s_cnt, 1);
                    if (p < NCAP) s_cand[p] = (klo << 16) | idx;
                }
                if (khi >= cur16) {
                    int p = atomicAdd(&s_cnt, 1);
                    if (p < NCAP) s_cand[p] = (khi << 16) | (idx + 1);
                }
            }
        }
        __syncthreads();
        M = s_cnt < NCAP ? s_cnt : NCAP;
    }

    // ---- exact fp32 rescore (one warp per candidate) ----
    for (int cc = warp; cc < M; cc += 16) {
        int c = (int)(s_cand[cc] & 0xFFFFu);
        float sq = 0.0f, sl = 0.0f;
        if (uni) {
            #pragma unroll
            for (int jj = 0; jj < 8; jj++) {
                int d = lane + (jj << 5);
                float m  = mean[(size_t)c * Dc + d];
                float xv = x[(size_t)b * Dc + d];
                float df = xv - m;
                sq = fmaf(df, df, sq);
            }
        } else {
            #pragma unroll
            for (int jj = 0; jj < 8; jj++) {
                int d = lane + (jj << 5);
                float m  = mean[(size_t)c * Dc + d];
                float sd = stddev[(size_t)c * Dc + d];
                float xv = x[(size_t)b * Dc + d];
                float iv = 1.0f / (sd * sd);
                float df = xv - m;
                sq = fmaf(df * df, iv, sq);
                sl += logf(sd);
            }
        }
        #pragma unroll
        for (int off = 16; off > 0; off >>= 1) {
            sq += __shfl_xor_sync(0xffffffffu, sq, off);
            sl += __shfl_xor_sync(0xffffffffu, sl, off);
        }
        if (lane == 0) s_clp[cc] = -0.5f * sq - sl - HALF_D_LOG2PI;
    }
    __syncthreads();

    // ---- exact top-32 of up to NCAP rescored values (warp 0, 4 slots/lane) ----
    if (warp == 0) {
        float va[4]; int ia[4];
        #pragma unroll
        for (int q = 0; q < 4; q++) { ia[q] = lane + q * 32; va[q] = s_clp[ia[q]]; }
        for (int r = 0; r < TOPK; r++) {
            float m = va[0]; int mi = ia[0];
            #pragma unroll
            for (int q = 1; q < 4; q++)
                if (va[q] > m) { m = va[q]; mi = ia[q]; }
            float bm = m; int bi = mi;
            #pragma unroll
            for (int off = 16; off > 0; off >>= 1) {
                float ov = __shfl_down_sync(0xffffffffu, bm, off);
                int   oi = __shfl_down_sync(0xffffffffu, bi, off);
                if (ov > bm) { bm = ov; bi = oi; }
            }
            bm = __shfl_sync(0xffffffffu, bm, 0);
            bi = __shfl_sync(0xffffffffu, bi, 0);
            if (lane == 0) { s_fv[r] = bm; s_fi[r] = (int)(s_cand[bi] & 0xFFFFu); }
            #pragma unroll
            for (int q = 0; q < 4; q++) if (ia[q] == bi) va[q] = NI;
        }
    }
    __syncthreads();

    if (t < TOPK) {
        float e = expf(s_fv[t] - s_fv[0]);
        float s = e;
        #pragma unroll
        for (int off = 16; off > 0; off >>= 1)
            s += __shfl_xor_sync(0xffffffffu, s, off);
        s_w[t] = e / s;
    }
    __syncthreads();

    int o = t & 255, g = t >> 8;   // g in {0,1}
    float p = 0.0f;
    #pragma unroll
    for (int j = 0; j < 16; j++) {
        int jj = g * 16 + j;
        p = fmaf(s_w[jj], outputs[(size_t)s_fi[jj] * Oc + o], p);
    }
    part[g * 256 + o] = p;
    __syncthreads();
    if (t < 256)
        out[(size_t)b * Oc + t] = part[t] + part[256 + t];
}

// ---------------- launch ----------------
extern "C" void kernel_launch(void* const* d_in, const int* in_sizes, int n_in,
                              void* d_out, int out_size) {
    const float* x       = (const float*)d_in[0];
    const float* mean    = (const float*)d_in[1];
    const float* stddev  = (const float*)d_in[2];
    const float* outputs = (const float*)d_in[3];
    float* out = (float*)d_out;

    cudaFuncSetAttribute(gemm_kernel, cudaFuncAttributeMaxDynamicSharedMemorySize, GEMM_SMEM);

    prep_x_kernel<<<Bc, Dc>>>(x);
    prep_w_kernel<<<Kc / 8, 256>>>(mean, stddev);
    prep_w_fix_kernel<<<Kc / 8, 256>>>(stddev);
    gemm_kernel<<<dim3(Bc / 128, Kc / 128), 128, GEMM_SMEM>>>();
    topk_kernel<<<Bc, 512>>>(x, mean, stddev, outputs, out);
}

// round 15
// speedup vs baseline: 1.4805x; 1.0372x over previous
#include <cuda_runtime.h>
#include <cuda_bf16.h>
#include <cuda_fp16.h>
#include <math.h>
#include <stdint.h>

#define Kc 65536
#define Dc 256
#define Oc 256
#define Bc 1024
#define TOPK 32
#define NCAND 48
#define NCAP 128
#define NTILES 512
#define TCAP 128
#define TWOD 512
#define SHIFT_FULL 491.25f
#define SHIFT_UNI  363.25f
#define HALF_D_LOG2PI 235.2482645f   // 0.5 * 256 * ln(2*pi)

// ---------------- device scratch ----------------
__device__ __nv_bfloat16 g_xb[(size_t)Bc * TWOD];        // 1 MB  [x | -0.5x^2]
__device__ __nv_bfloat16 g_wb[(size_t)Kc * TWOD];        // 64 MB [m*iv | iv]
__device__ float         g_bias[Kc];
__device__ __half        g_lh[(size_t)Bc * Kc];          // 128 MB shifted logits
__device__ __half        g_tmax[(size_t)Bc * NTILES];    // 1 MB per-row per-tile max (fp16)
__device__ int           g_flag;                          // 1 => stddev == 1 everywhere

__device__ __forceinline__ float neg_inf() { return __int_as_float(0xff800000); }

__device__ __forceinline__ uint32_t smem_u32(const void* p) {
    uint32_t a;
    asm("{ .reg .u64 t; cvta.to.shared.u64 t, %1; cvt.u32.u64 %0, t; }" : "=r"(a) : "l"(p));
    return a;
}
__device__ __forceinline__ void cp_async16(uint32_t dst, const void* src) {
    asm volatile("cp.async.cg.shared.global [%0], [%1], 16;" :: "r"(dst), "l"(src));
}
#define CP_COMMIT() asm volatile("cp.async.commit_group;" ::: "memory")
#define CP_WAIT(n)  asm volatile("cp.async.wait_group %0;" :: "n"(n) : "memory")

#define LDSM_X4(r, addr) \
    asm volatile("ldmatrix.sync.aligned.m8n8.x4.shared.b16 {%0,%1,%2,%3}, [%4];" \
        : "=r"((r)[0]), "=r"((r)[1]), "=r"((r)[2]), "=r"((r)[3]) : "r"(addr))

__device__ __forceinline__ void mma16816(float* c, const uint32_t* a, uint32_t b0, uint32_t b1) {
    asm volatile("mma.sync.aligned.m16n8k16.row.col.f32.bf16.bf16.f32 "
        "{%0,%1,%2,%3}, {%4,%5,%6,%7}, {%8,%9}, {%0,%1,%2,%3};"
        : "+f"(c[0]), "+f"(c[1]), "+f"(c[2]), "+f"(c[3])
        : "r"(a[0]), "r"(a[1]), "r"(a[2]), "r"(a[3]), "r"(b0), "r"(b1));
}

// both halves of a half2 word -> order-preserving 16-bit keys
__device__ __forceinline__ uint32_t key2(uint32_t h2) {
    uint32_t s = h2 & 0x80008000u;
    uint32_t m = 0x80008000u | ((s >> 15) * 0x7FFFu);
    return h2 ^ m;
}
__device__ __forceinline__ uint32_t hkey(uint32_t h) {   // single fp16 bits -> 16-bit key
    return h ^ ((h & 0x8000u) ? 0xFFFFu : 0x8000u);
}

// ---------------- prep kernels ----------------
__global__ void prep_x_kernel(const float* __restrict__ x) {
    int b = blockIdx.x, d = threadIdx.x;
    float v = x[b * Dc + d];
    g_xb[(size_t)b * TWOD + d]      = __float2bfloat16(v);
    g_xb[(size_t)b * TWOD + Dc + d] = __float2bfloat16(-0.5f * v * v);
    if (b == 0 && d == 0) g_flag = 1;   // reset each launch (graph-replay safe)
}

// warp per k-row, lane handles 8 elements; writes only the m*iv half (32 MB)
__global__ void __launch_bounds__(256) prep_w_kernel(const float* __restrict__ mean,
                                                     const float* __restrict__ stddev) {
    int warp = threadIdx.x >> 5, lane = threadIdx.x & 31;
    int k = blockIdx.x * 8 + warp;
    int e = lane * 8;
    const float* mp = mean   + (size_t)k * Dc + e;
    const float* sp = stddev + (size_t)k * Dc + e;
    float4 ma = *(const float4*)mp,      mb = *(const float4*)(mp + 4);
    float4 sa = *(const float4*)sp,      sb = *(const float4*)(sp + 4);

    bool nonuni = (sa.x != 1.0f) | (sa.y != 1.0f) | (sa.z != 1.0f) | (sa.w != 1.0f) |
                  (sb.x != 1.0f) | (sb.y != 1.0f) | (sb.z != 1.0f) | (sb.w != 1.0f);
    if (nonuni) g_flag = 0;

    float m8[8] = {ma.x, ma.y, ma.z, ma.w, mb.x, mb.y, mb.z, mb.w};
    float s8[8] = {sa.x, sa.y, sa.z, sa.w, sb.x, sb.y, sb.z, sb.w};
    float part = 0.0f;
    __nv_bfloat16 w8[8];
    #pragma unroll
    for (int i = 0; i < 8; i++) {
        float iv = 1.0f / (s8[i] * s8[i]);
        float miv = m8[i] * iv;
        w8[i] = __float2bfloat16(miv);
        part = fmaf(-0.5f * m8[i], miv, part);
    }
    if (nonuni) {
        #pragma unroll
        for (int i = 0; i < 8; i++) part -= logf(s8[i]);
    }
    *(uint4*)&g_wb[(size_t)k * TWOD + e] = *(uint4*)w8;

    #pragma unroll
    for (int off = 16; off > 0; off >>= 1)
        part += __shfl_xor_sync(0xffffffffu, part, off);
    if (lane == 0) g_bias[k] = part - HALF_D_LOG2PI;
}

// fix-up: writes the iv half; runs only when some stddev != 1
__global__ void __launch_bounds__(256) prep_w_fix_kernel(const float* __restrict__ stddev) {
    if (g_flag) return;
    int warp = threadIdx.x >> 5, lane = threadIdx.x & 31;
    int k = blockIdx.x * 8 + warp;
    int e = lane * 8;
    const float* sp = stddev + (size_t)k * Dc + e;
    float4 sa = *(const float4*)sp, sb = *(const float4*)(sp + 4);
    float s8[8] = {sa.x, sa.y, sa.z, sa.w, sb.x, sb.y, sb.z, sb.w};
    __nv_bfloat16 w8[8];
    #pragma unroll
    for (int i = 0; i < 8; i++)
        w8[i] = __float2bfloat16(1.0f / (s8[i] * s8[i]));
    *(uint4*)&g_wb[(size_t)k * TWOD + Dc + e] = *(uint4*)w8;
}

// ---------------- mma.sync bf16 GEMM (+ per-tile row max) ----------------
// 128x128 CTA tile, 4 warps (2x2), 64x64 warp tiles.
// Fragment double-buffering: LDSM for the NEXT ks-half issued before the
// current half's MMAs (incl. across the iteration boundary).
#define NSTAGE 4
#define ROWB   80
#define STAGE_BYTES (128 * ROWB * 2)   // A + B per stage = 20480
#define GEMM_SMEM (NSTAGE * STAGE_BYTES)
#define STGROW 272                      // staging row stride (bytes)

__device__ __forceinline__ void load_stage(uint32_t sbase, int st, int m0, int n0, int k0, int tid) {
    uint32_t ab = sbase + st * STAGE_BYTES;
    uint32_t bb = ab + 128 * ROWB;
    #pragma unroll
    for (int i = 0; i < 4; i++) {
        int lin = tid + (i << 7);
        int row = lin >> 2, ch = lin & 3;
        cp_async16(ab + row * ROWB + ch * 16, g_xb + (size_t)(m0 + row) * TWOD + k0 + ch * 8);
        cp_async16(bb + row * ROWB + ch * 16, g_wb + (size_t)(n0 + row) * TWOD + k0 + ch * 8);
    }
    CP_COMMIT();
}

#define LDSM_FRAGS(afr, bfr, stb, ksoff) do { \
    uint32_t _ab = (stb); \
    uint32_t _bb = _ab + 128 * ROWB; \
    _Pragma("unroll") \
    for (int _mt = 0; _mt < 4; _mt++) \
        LDSM_X4((afr)[_mt], _ab + a_off + _mt * (16 * ROWB) + (ksoff)); \
    _Pragma("unroll") \
    for (int _np = 0; _np < 4; _np++) \
        LDSM_X4((bfr)[_np], _bb + b_off + _np * (16 * ROWB) + (ksoff)); \
} while (0)

#define MMA_ALL(afr, bfr) do { \
    _Pragma("unroll") \
    for (int _mt = 0; _mt < 4; _mt++) \
        _Pragma("unroll") \
        for (int _nt = 0; _nt < 8; _nt++) \
            mma16816(acc[_mt][_nt], (afr)[_mt], \
                     (bfr)[_nt >> 1][(_nt & 1) * 2], (bfr)[_nt >> 1][(_nt & 1) * 2 + 1]); \
} while (0)

__global__ void __launch_bounds__(128, 2) gemm_kernel() {
    extern __shared__ char smem[];
    __shared__ float smax[128][2];
    uint32_t sbase = smem_u32(smem);
    int tid = threadIdx.x, wid = tid >> 5, lane = tid & 31;
    int m0 = blockIdx.x * 128;            // M fastest: consecutive CTAs share B tile
    int n0 = blockIdx.y * 128;
    int wm = wid >> 1, wn = wid & 1;

    int uni = g_flag;
    int KT = uni ? 8 : 16;
    float SHIFTV = uni ? SHIFT_UNI : SHIFT_FULL;

    float acc[4][8][4];
    #pragma unroll
    for (int mt = 0; mt < 4; mt++)
        #pragma unroll
        for (int nt = 0; nt < 8; nt++)
            #pragma unroll
            for (int q = 0; q < 4; q++) acc[mt][nt][q] = 0.0f;

    load_stage(sbase, 0, m0, n0, 0, tid);
    load_stage(sbase, 1, m0, n0, 32, tid);
    load_stage(sbase, 2, m0, n0, 64, tid);

    uint32_t a_row = (uint32_t)(wm * 64 + (lane & 15));
    uint32_t a_off = a_row * ROWB + ((lane >> 4) << 4);
    uint32_t b_row = (uint32_t)(wn * 64 + (lane & 7) + ((lane >> 4) << 3));
    uint32_t b_off = b_row * ROWB + (((lane >> 3) & 1) << 4);

    uint32_t afr0[4][4], bfr0[4][4];   // buf0: ks=0 fragments
    uint32_t afr1[4][4], bfr1[4][4];   // buf1: ks=1 fragments

    CP_WAIT(2);            // drains group 0
    __syncthreads();
    LDSM_FRAGS(afr0, bfr0, sbase + 0 * STAGE_BYTES, 0);   // (it=0, ks=0)

    #pragma unroll 1
    for (int it = 0; it < KT; it++) {
        __syncthreads();   // all reads of stage (it-1)%4 done before its rewrite
        if (it + 3 < KT) load_stage(sbase, (it + 3) % NSTAGE, m0, n0, (it + 3) * 32, tid);
        else CP_COMMIT();
        CP_WAIT(2);        // drains group it+1 (next iteration's stage)

        uint32_t stb = sbase + (it % NSTAGE) * STAGE_BYTES;

        // ks = 0: prefetch ks=1 fragments, then MMA on buf0
        LDSM_FRAGS(afr1, bfr1, stb, 32);
        MMA_ALL(afr0, bfr0);

        // ks = 1: prefetch next iteration's ks=0 fragments, then MMA on buf1
        if (it + 1 < KT) {
            uint32_t stb2 = sbase + ((it + 1) % NSTAGE) * STAGE_BYTES;
            LDSM_FRAGS(afr0, bfr0, stb2, 0);
        }
        MMA_ALL(afr1, bfr1);
    }
    CP_WAIT(0);
    __syncthreads();   // all ldmatrix done: staging may overwrite pipeline smem

    const float NI = neg_inf();
    float rmA[4], rmB[4];
    #pragma unroll
    for (int mt = 0; mt < 4; mt++) { rmA[mt] = NI; rmB[mt] = NI; }

    // stage converted half2 into smem (conflict-free: 272B row stride)
    #pragma unroll
    for (int nt = 0; nt < 8; nt++) {
        int col = wn * 64 + nt * 8 + (lane & 3) * 2;
        float2 bb2 = *(const float2*)&g_bias[n0 + col];
        float bx = bb2.x + SHIFTV, by = bb2.y + SHIFTV;
        #pragma unroll
        for (int mt = 0; mt < 4; mt++) {
            int rowl = wm * 64 + mt * 16 + (lane >> 2);
            float a0 = acc[mt][nt][0] + bx, a1 = acc[mt][nt][1] + by;
            float a2 = acc[mt][nt][2] + bx, a3 = acc[mt][nt][3] + by;
            rmA[mt] = fmaxf(rmA[mt], fmaxf(a0, a1));
            rmB[mt] = fmaxf(rmB[mt], fmaxf(a2, a3));
            *(__half2*)(smem + rowl * STGROW + col * 2)       = __floats2half2_rn(a0, a1);
            *(__half2*)(smem + (rowl + 8) * STGROW + col * 2) = __floats2half2_rn(a2, a3);
        }
    }

    #pragma unroll
    for (int mt = 0; mt < 4; mt++) {
        #pragma unroll
        for (int off = 1; off < 4; off <<= 1) {
            rmA[mt] = fmaxf(rmA[mt], __shfl_xor_sync(0xffffffffu, rmA[mt], off));
            rmB[mt] = fmaxf(rmB[mt], __shfl_xor_sync(0xffffffffu, rmB[mt], off));
        }
        if ((lane & 3) == 0) {
            int lr = wm * 64 + mt * 16 + (lane >> 2);
            smax[lr][wn]     = rmA[mt];
            smax[lr + 8][wn] = rmB[mt];
        }
    }
    __syncthreads();

    // coalesced copy-out: 128 rows x 256B = 2048 uint4, 16 per thread
    #pragma unroll
    for (int i = 0; i < 16; i++) {
        int lin = tid + (i << 7);
        int r = lin >> 4, q = lin & 15;
        uint4 v = *(const uint4*)(smem + r * STGROW + q * 16);
        *(uint4*)(g_lh + (size_t)(m0 + r) * Kc + n0 + q * 8) = v;
    }

    {
        float m = fmaxf(smax[tid][0], smax[tid][1]);
        // rn is monotonic: half(max fp32) == max over tile of half(v)
        g_tmax[(size_t)(m0 + tid) * NTILES + blockIdx.y] = __float2half(m);
    }
}

// ---------------- topk: tile-max threshold IS the value threshold ----------------
__global__ void __launch_bounds__(512) topk_kernel(const float* __restrict__ x,
                                                   const float* __restrict__ mean,
                                                   const float* __restrict__ stddev,
                                                   const float* __restrict__ outputs,
                                                   float* __restrict__ out) {
    int b = blockIdx.x, t = threadIdx.x;
    int lane = t & 31, warp = t >> 5;
    const float NI = neg_inf();
    int uni = g_flag;

    __shared__ int   s_tiles[TCAP];
    __shared__ int   s_nt, s_cnt;
    __shared__ int   sred[16];
    __shared__ uint32_t s_cand[NCAP];
    __shared__ float s_clp[NCAP];
    __shared__ float s_fv[TOPK];
    __shared__ int   s_fi[TOPK];
    __shared__ float s_w[TOPK];
    __shared__ float part[2 * 256];

    // ---- stage 1: cur = key of the NCAND-th largest tile max (16 vote rounds) ----
    uint32_t tk = hkey((uint32_t)__half_as_ushort(g_tmax[(size_t)b * NTILES + t]));
    uint32_t cur = 0;
    #pragma unroll 1
    for (int bit = 15; bit >= 0; --bit) {
        uint32_t T = cur | (1u << bit);
        int n = __syncthreads_count(tk >= T);
        if (n >= NCAND) cur = T;
    }
    if (t == 0) { s_nt = 0; s_cnt = 0; }
    __syncthreads();
    if (tk >= cur) {
        int p = atomicAdd(&s_nt, 1);
        if (p < TCAP) s_tiles[p] = t;
    }
    if (t < NCAP) s_clp[t] = NI;
    __syncthreads();
    int ntl = s_nt < TCAP ? s_nt : TCAP;
    int total = ntl * 64;          // u32 words across selected tiles

    // ---- stage 2: collect values with key >= cur directly (no second search) ----
    const uint32_t* row32 = (const uint32_t*)(g_lh + (size_t)b * Kc);
    #pragma unroll 4
    for (int i = 0; i < 16; i++) {
        int w = t + (i << 9);
        if (w < total) {
            int tile = s_tiles[w >> 6];
            uint32_t k2 = key2(row32[tile * 64 + (w & 63)]);
            uint32_t klo = k2 & 0xFFFFu, khi = k2 >> 16;
            uint32_t idx = (uint32_t)(tile * 128 + (w & 63) * 2);
            if (klo >= cur) {
                int p = atomicAdd(&s_cnt, 1);
                if (p < NCAP) s_cand[p] = (klo << 16) | idx;
            }
            if (khi >= cur) {
                int p = atomicAdd(&s_cnt, 1);
                if (p < NCAP) s_cand[p] = (khi << 16) | (idx + 1);
            }
        }
    }
    __syncthreads();
    int M = s_cnt;

    if (M > NCAP) {
        // ---- exact fallback (overflow; probability ~0): full 16-bit threshold search ----
        uint32_t u[16];
        #pragma unroll
        for (int i = 0; i < 16; i++) {
            int w = t + (i << 9);
            u[i] = (w < total) ? key2(row32[s_tiles[w >> 6] * 64 + (w & 63)]) : 0x03FF03FFu;
        }
        uint32_t cur16 = 0;
        #pragma unroll 1
        for (int bit = 15; bit >= 0; --bit) {
            uint32_t T = cur16 | (1u << bit);
            int c = 0;
            #pragma unroll
            for (int i = 0; i < 16; i++)
                c += ((u[i] & 0xFFFFu) >= T) + ((u[i] >> 16) >= T);
            #pragma unroll
            for (int off = 16; off > 0; off >>= 1)
                c += __shfl_xor_sync(0xffffffffu, c, off);
            __syncthreads();
            if (lane == 0) sred[warp] = c;
            __syncthreads();
            int n = 0;
            #pragma unroll
            for (int w2 = 0; w2 < 16; w2++) n += sred[w2];
            if (n >= NCAND) cur16 = T;
        }
        if (t == 0) s_cnt = 0;
        __syncthreads();
        #pragma unroll
        for (int i = 0; i < 16; i++) {
            int w = t + (i << 9);
            if (w < total) {
                uint32_t klo = u[i] & 0xFFFFu, khi = u[i] >> 16;
                uint32_t idx = (uint32_t)(s_tiles[w >> 6] * 128 + (w & 63) * 2);
                if (klo >= cur16) {
                    int p = atomicAdd(&s_cnt, 1);
                    if (p < NCAP) s_cand[p] = (klo << 16) | idx;
                }
                if (khi >= cur16) {
                    int p = atomicAdd(&s_cnt, 1);
                    if (p < NCAP) s_cand[p] = (khi << 16) | (idx + 1);
                }
            }
        }
        __syncthreads();
        M = s_cnt < NCAP ? s_cnt : NCAP;
    }

    // ---- exact fp32 rescore (one warp per candidate) ----
    for (int cc = warp; cc < M; cc += 16) {
        int c = (int)(s_cand[cc] & 0xFFFFu);
        float sq = 0.0f, sl = 0.0f;
        if (uni) {
            #pragma unroll
            for (int jj = 0; jj < 8; jj++) {
                int d = lane + (jj << 5);
                float m  = mean[(size_t)c * Dc + d];
                float xv = x[(size_t)b * Dc + d];
                float df = xv - m;
                sq = fmaf(df, df, sq);
            }
        } else {
            #pragma unroll
            for (int jj = 0; jj < 8; jj++) {
                int d = lane + (jj << 5);
                float m  = mean[(size_t)c * Dc + d];
                float sd = stddev[(size_t)c * Dc + d];
                float xv = x[(size_t)b * Dc + d];
                float iv = 1.0f / (sd * sd);
                float df = xv - m;
                sq = fmaf(df * df, iv, sq);
                sl += logf(sd);
            }
        }
        #pragma unroll
        for (int off = 16; off > 0; off >>= 1) {
            sq += __shfl_xor_sync(0xffffffffu, sq, off);
            sl += __shfl_xor_sync(0xffffffffu, sl, off);
        }
        if (lane == 0) s_clp[cc] = -0.5f * sq - sl - HALF_D_LOG2PI;
    }
    __syncthreads();

    // ---- exact top-32 of up to NCAP rescored values (warp 0, 4 slots/lane) ----
    if (warp == 0) {
        float va[4]; int ia[4];
        #pragma unroll
        for (int q = 0; q < 4; q++) { ia[q] = lane + q * 32; va[q] = s_clp[ia[q]]; }
        for (int r = 0; r < TOPK; r++) {
            float m = va[0]; int mi = ia[0];
            #pragma unroll
            for (int q = 1; q < 4; q++)
                if (va[q] > m) { m = va[q]; mi = ia[q]; }
            float bm = m; int bi = mi;
            #pragma unroll
            for (int off = 16; off > 0; off >>= 1) {
                float ov = __shfl_down_sync(0xffffffffu, bm, off);
                int   oi = __shfl_down_sync(0xffffffffu, bi, off);
                if (ov > bm) { bm = ov; bi = oi; }
            }
            bm = __shfl_sync(0xffffffffu, bm, 0);
            bi = __shfl_sync(0xffffffffu, bi, 0);
            if (lane == 0) { s_fv[r] = bm; s_fi[r] = (int)(s_cand[bi] & 0xFFFFu); }
            #pragma unroll
            for (int q = 0; q < 4; q++) if (ia[q] == bi) va[q] = NI;
        }
    }
    __syncthreads();

    if (t < TOPK) {
        float e = expf(s_fv[t] - s_fv[0]);
        float s = e;
        #pragma unroll
        for (int off = 16; off > 0; off >>= 1)
            s += __shfl_xor_sync(0xffffffffu, s, off);
        s_w[t] = e / s;
    }
    __syncthreads();

    int o = t & 255, g = t >> 8;   // g in {0,1}
    float p = 0.0f;
    #pragma unroll
    for (int j = 0; j < 16; j++) {
        int jj = g * 16 + j;
        p = fmaf(s_w[jj], outputs[(size_t)s_fi[jj] * Oc + o], p);
    }
    part[g * 256 + o] = p;
    __syncthreads();
    if (t < 256)
        out[(size_t)b * Oc + t] = part[t] + part[256 + t];
}

// ---------------- launch ----------------
extern "C" void kernel_launch(void* const* d_in, const int* in_sizes, int n_in,
                              void* d_out, int out_size) {
    const float* x       = (const float*)d_in[0];
    const float* mean    = (const float*)d_in[1];
    const float* stddev  = (const float*)d_in[2];
    const float* outputs = (const float*)d_in[3];
    float* out = (float*)d_out;

    cudaFuncSetAttribute(gemm_kernel, cudaFuncAttributeMaxDynamicSharedMemorySize, GEMM_SMEM);

    prep_x_kernel<<<Bc, Dc>>>(x);
    prep_w_kernel<<<Kc / 8, 256>>>(mean, stddev);
    prep_w_fix_kernel<<<Kc / 8, 256>>>(stddev);
    gemm_kernel<<<dim3(Bc / 128, Kc / 128), 128, GEMM_SMEM>>>();
    topk_kernel<<<Bc, 512>>>(x, mean, stddev, outputs, out);
}

// round 16
// speedup vs baseline: 1.6735x; 1.1304x over previous
#include <cuda_runtime.h>
#include <cuda_bf16.h>
#include <cuda_fp16.h>
#include <math.h>
#include <stdint.h>

#define Kc 65536
#define Dc 256
#define Oc 256
#define Bc 1024
#define TOPK 32
#define NCAND 48
#define NCAP 128
#define NTILES 512
#define TCAP 128
#define TWOD 512
#define SHIFT_FULL 491.25f
#define SHIFT_UNI  363.25f
#define HALF_D_LOG2PI 235.2482645f   // 0.5 * 256 * ln(2*pi)

// ---------------- device scratch ----------------
__device__ __nv_bfloat16 g_xb[(size_t)Bc * TWOD];        // 1 MB  [x | -0.5x^2]
__device__ __nv_bfloat16 g_wb[(size_t)Kc * TWOD];        // 64 MB [m*iv | iv]
__device__ float         g_bias[Kc];
__device__ __half        g_lh[(size_t)Bc * Kc];          // 128 MB shifted logits
__device__ __half        g_tmax[(size_t)Bc * NTILES];    // 1 MB per-row per-tile max (fp16)
__device__ int           g_flag;                          // 1 => stddev == 1 everywhere

__device__ __forceinline__ float neg_inf() { return __int_as_float(0xff800000); }

__device__ __forceinline__ uint32_t smem_u32(const void* p) {
    uint32_t a;
    asm("{ .reg .u64 t; cvta.to.shared.u64 t, %1; cvt.u32.u64 %0, t; }" : "=r"(a) : "l"(p));
    return a;
}
__device__ __forceinline__ void cp_async16(uint32_t dst, const void* src) {
    asm volatile("cp.async.cg.shared.global [%0], [%1], 16;" :: "r"(dst), "l"(src));
}
#define CP_COMMIT() asm volatile("cp.async.commit_group;" ::: "memory")
#define CP_WAIT(n)  asm volatile("cp.async.wait_group %0;" :: "n"(n) : "memory")

#define LDSM_X4(r, addr) \
    asm volatile("ldmatrix.sync.aligned.m8n8.x4.shared.b16 {%0,%1,%2,%3}, [%4];" \
        : "=r"((r)[0]), "=r"((r)[1]), "=r"((r)[2]), "=r"((r)[3]) : "r"(addr))

__device__ __forceinline__ void mma16816(float* c, const uint32_t* a, uint32_t b0, uint32_t b1) {
    asm volatile("mma.sync.aligned.m16n8k16.row.col.f32.bf16.bf16.f32 "
        "{%0,%1,%2,%3}, {%4,%5,%6,%7}, {%8,%9}, {%0,%1,%2,%3};"
        : "+f"(c[0]), "+f"(c[1]), "+f"(c[2]), "+f"(c[3])
        : "r"(a[0]), "r"(a[1]), "r"(a[2]), "r"(a[3]), "r"(b0), "r"(b1));
}

// both halves of a half2 word -> order-preserving 16-bit keys
__device__ __forceinline__ uint32_t key2(uint32_t h2) {
    uint32_t s = h2 & 0x80008000u;
    uint32_t m = 0x80008000u | ((s >> 15) * 0x7FFFu);
    return h2 ^ m;
}
__device__ __forceinline__ uint32_t hkey(uint32_t h) {   // single fp16 bits -> 16-bit key
    return h ^ ((h & 0x8000u) ? 0xFFFFu : 0x8000u);
}

// ---------------- prep kernels ----------------
__global__ void prep_x_kernel(const float* __restrict__ x) {
    int b = blockIdx.x, d = threadIdx.x;
    float v = x[b * Dc + d];
    g_xb[(size_t)b * TWOD + d]      = __float2bfloat16(v);
    g_xb[(size_t)b * TWOD + Dc + d] = __float2bfloat16(-0.5f * v * v);
    if (b == 0 && d == 0) g_flag = 1;   // reset each launch (graph-replay safe)
}

// warp per k-row, lane handles 8 elements; writes only the m*iv half (32 MB)
__global__ void __launch_bounds__(256) prep_w_kernel(const float* __restrict__ mean,
                                                     const float* __restrict__ stddev) {
    int warp = threadIdx.x >> 5, lane = threadIdx.x & 31;
    int k = blockIdx.x * 8 + warp;
    int e = lane * 8;
    const float* mp = mean   + (size_t)k * Dc + e;
    const float* sp = stddev + (size_t)k * Dc + e;
    float4 ma = *(const float4*)mp,      mb = *(const float4*)(mp + 4);
    float4 sa = *(const float4*)sp,      sb = *(const float4*)(sp + 4);

    bool nonuni = (sa.x != 1.0f) | (sa.y != 1.0f) | (sa.z != 1.0f) | (sa.w != 1.0f) |
                  (sb.x != 1.0f) | (sb.y != 1.0f) | (sb.z != 1.0f) | (sb.w != 1.0f);
    if (nonuni) g_flag = 0;

    float m8[8] = {ma.x, ma.y, ma.z, ma.w, mb.x, mb.y, mb.z, mb.w};
    float s8[8] = {sa.x, sa.y, sa.z, sa.w, sb.x, sb.y, sb.z, sb.w};
    float part = 0.0f;
    __nv_bfloat16 w8[8];
    #pragma unroll
    for (int i = 0; i < 8; i++) {
        float iv = 1.0f / (s8[i] * s8[i]);
        float miv = m8[i] * iv;
        w8[i] = __float2bfloat16(miv);
        part = fmaf(-0.5f * m8[i], miv, part);
    }
    if (nonuni) {
        #pragma unroll
        for (int i = 0; i < 8; i++) part -= logf(s8[i]);
    }
    *(uint4*)&g_wb[(size_t)k * TWOD + e] = *(uint4*)w8;

    #pragma unroll
    for (int off = 16; off > 0; off >>= 1)
        part += __shfl_xor_sync(0xffffffffu, part, off);
    if (lane == 0) g_bias[k] = part - HALF_D_LOG2PI;
}

// fix-up: writes the iv half; runs only when some stddev != 1
__global__ void __launch_bounds__(256) prep_w_fix_kernel(const float* __restrict__ stddev) {
    if (g_flag) return;
    int warp = threadIdx.x >> 5, lane = threadIdx.x & 31;
    int k = blockIdx.x * 8 + warp;
    int e = lane * 8;
    const float* sp = stddev + (size_t)k * Dc + e;
    float4 sa = *(const float4*)sp, sb = *(const float4*)(sp + 4);
    float s8[8] = {sa.x, sa.y, sa.z, sa.w, sb.x, sb.y, sb.z, sb.w};
    __nv_bfloat16 w8[8];
    #pragma unroll
    for (int i = 0; i < 8; i++)
        w8[i] = __float2bfloat16(1.0f / (s8[i] * s8[i]));
    *(uint4*)&g_wb[(size_t)k * TWOD + Dc + e] = *(uint4*)w8;
}

// ---------------- mma.sync bf16 GEMM (+ per-tile row max) ----------------
// 128x128 CTA tile, 4 warps (2x2), 64x64 warp tiles, BK=64, XOR-swizzled
// 128B smem rows (chunk ^= row&7 keeps ldmatrix conflict-free, no padding).
// Fragment double-buffering across the 4 ks-halves and across iterations.
#define NSTAGE 3
#define STAGE_BYTES 32768              // A[128x128B] + B[128x128B]
#define GEMM_SMEM (NSTAGE * STAGE_BYTES)
#define STGROW 272                      // staging row stride (bytes)

__device__ __forceinline__ void load_stage(uint32_t sbase, int st, int m0, int n0, int k0, int tid) {
    uint32_t ab = sbase + st * STAGE_BYTES;
    uint32_t bb = ab + 16384;
    #pragma unroll
    for (int i = 0; i < 8; i++) {
        int lin = tid + (i << 7);
        int row = lin >> 3, ch = lin & 7;
        uint32_t off = (uint32_t)row * 128u + ((uint32_t)(ch ^ (row & 7)) << 4);
        cp_async16(ab + off, g_xb + (size_t)(m0 + row) * TWOD + k0 + ch * 8);
        cp_async16(bb + off, g_wb + (size_t)(n0 + row) * TWOD + k0 + ch * 8);
    }
    CP_COMMIT();
}

#define LDSM_FRAGS(afr, bfr, stb, ks) do { \
    uint32_t _ab = (stb) + a_base + axk[ks]; \
    uint32_t _bb = (stb) + 16384 + b_base + bxk[ks]; \
    _Pragma("unroll") \
    for (int _mt = 0; _mt < 4; _mt++) \
        LDSM_X4((afr)[_mt], _ab + _mt * 2048); \
    _Pragma("unroll") \
    for (int _np = 0; _np < 4; _np++) \
        LDSM_X4((bfr)[_np], _bb + _np * 2048); \
} while (0)

#define MMA_ALL(afr, bfr) do { \
    _Pragma("unroll") \
    for (int _mt = 0; _mt < 4; _mt++) \
        _Pragma("unroll") \
        for (int _nt = 0; _nt < 8; _nt++) \
            mma16816(acc[_mt][_nt], (afr)[_mt], \
                     (bfr)[_nt >> 1][(_nt & 1) * 2], (bfr)[_nt >> 1][(_nt & 1) * 2 + 1]); \
} while (0)

__global__ void __launch_bounds__(128, 2) gemm_kernel() {
    extern __shared__ char smem[];
    __shared__ float smax[128][2];
    uint32_t sbase = smem_u32(smem);
    int tid = threadIdx.x, wid = tid >> 5, lane = tid & 31;
    int m0 = blockIdx.x * 128;            // M fastest: consecutive CTAs share B tile
    int n0 = blockIdx.y * 128;
    int wm = wid >> 1, wn = wid & 1;

    int uni = g_flag;
    int KTB = uni ? 4 : 8;                // 64-wide k slices
    float SHIFTV = uni ? SHIFT_UNI : SHIFT_FULL;

    float acc[4][8][4];
    #pragma unroll
    for (int mt = 0; mt < 4; mt++)
        #pragma unroll
        for (int nt = 0; nt < 8; nt++)
            #pragma unroll
            for (int q = 0; q < 4; q++) acc[mt][nt][q] = 0.0f;

    load_stage(sbase, 0, m0, n0, 0, tid);
    load_stage(sbase, 1, m0, n0, 64, tid);

    // XOR-swizzled fragment addressing (per-thread constants)
    int a_r = wm * 64 + (lane & 15);
    int hiA = lane >> 4;
    uint32_t a_base = (uint32_t)a_r * 128u;
    int r7a = a_r & 7;
    int b_r = wn * 64 + (lane & 7) + ((lane >> 4) << 3);
    int hiB = (lane >> 3) & 1;
    uint32_t b_base = (uint32_t)b_r * 128u;
    int r7b = b_r & 7;
    uint32_t axk[4], bxk[4];
    #pragma unroll
    for (int ks = 0; ks < 4; ks++) {
        axk[ks] = (uint32_t)((ks * 2 + hiA) ^ r7a) << 4;
        bxk[ks] = (uint32_t)((ks * 2 + hiB) ^ r7b) << 4;
    }

    uint32_t afr0[4][4], bfr0[4][4];
    uint32_t afr1[4][4], bfr1[4][4];

    CP_WAIT(1);            // stage 0 complete (own groups)
    __syncthreads();
    LDSM_FRAGS(afr0, bfr0, sbase, 0);

    #pragma unroll 1
    for (int it = 0; it < KTB; it++) {
        __syncthreads();   // all reads of slot (it+2)%3 (from iter it-1) done
        if (it + 2 < KTB) load_stage(sbase, (it + 2) % NSTAGE, m0, n0, (it + 2) * 64, tid);
        else CP_COMMIT();
        CP_WAIT(1);        // stages it and it+1 complete (own groups)

        uint32_t stb = sbase + (it % NSTAGE) * STAGE_BYTES;

        LDSM_FRAGS(afr1, bfr1, stb, 1);
        MMA_ALL(afr0, bfr0);
        LDSM_FRAGS(afr0, bfr0, stb, 2);
        MMA_ALL(afr1, bfr1);
        LDSM_FRAGS(afr1, bfr1, stb, 3);
        MMA_ALL(afr0, bfr0);
        if (it + 1 < KTB) {
            uint32_t stb2 = sbase + ((it + 1) % NSTAGE) * STAGE_BYTES;
            LDSM_FRAGS(afr0, bfr0, stb2, 0);
        }
        MMA_ALL(afr1, bfr1);
    }
    CP_WAIT(0);
    __syncthreads();   // all ldmatrix done: staging may overwrite pipeline smem

    const float NI = neg_inf();
    float rmA[4], rmB[4];
    #pragma unroll
    for (int mt = 0; mt < 4; mt++) { rmA[mt] = NI; rmB[mt] = NI; }

    // stage converted half2 into smem (conflict-free: 272B row stride)
    #pragma unroll
    for (int nt = 0; nt < 8; nt++) {
        int col = wn * 64 + nt * 8 + (lane & 3) * 2;
        float2 bb2 = *(const float2*)&g_bias[n0 + col];
        float bx = bb2.x + SHIFTV, by = bb2.y + SHIFTV;
        #pragma unroll
        for (int mt = 0; mt < 4; mt++) {
            int rowl = wm * 64 + mt * 16 + (lane >> 2);
            float a0 = acc[mt][nt][0] + bx, a1 = acc[mt][nt][1] + by;
            float a2 = acc[mt][nt][2] + bx, a3 = acc[mt][nt][3] + by;
            rmA[mt] = fmaxf(rmA[mt], fmaxf(a0, a1));
            rmB[mt] = fmaxf(rmB[mt], fmaxf(a2, a3));
            *(__half2*)(smem + rowl * STGROW + col * 2)       = __floats2half2_rn(a0, a1);
            *(__half2*)(smem + (rowl + 8) * STGROW + col * 2) = __floats2half2_rn(a2, a3);
        }
    }

    #pragma unroll
    for (int mt = 0; mt < 4; mt++) {
        #pragma unroll
        for (int off = 1; off < 4; off <<= 1) {
            rmA[mt] = fmaxf(rmA[mt], __shfl_xor_sync(0xffffffffu, rmA[mt], off));
            rmB[mt] = fmaxf(rmB[mt], __shfl_xor_sync(0xffffffffu, rmB[mt], off));
        }
        if ((lane & 3) == 0) {
            int lr = wm * 64 + mt * 16 + (lane >> 2);
            smax[lr][wn]     = rmA[mt];
            smax[lr + 8][wn] = rmB[mt];
        }
    }
    __syncthreads();

    // coalesced copy-out: 128 rows x 256B = 2048 uint4, 16 per thread
    #pragma unroll
    for (int i = 0; i < 16; i++) {
        int lin = tid + (i << 7);
        int r = lin >> 4, q = lin & 15;
        uint4 v = *(const uint4*)(smem + r * STGROW + q * 16);
        *(uint4*)(g_lh + (size_t)(m0 + r) * Kc + n0 + q * 8) = v;
    }

    {
        float m = fmaxf(smax[tid][0], smax[tid][1]);
        // rn is monotonic: half(max fp32) == max over tile of half(v)
        g_tmax[(size_t)(m0 + tid) * NTILES + blockIdx.y] = __float2half(m);
    }
}

// ---------------- topk: tile-max threshold IS the value threshold ----------------
__global__ void __launch_bounds__(512) topk_kernel(const float* __restrict__ x,
                                                   const float* __restrict__ mean,
                                                   const float* __restrict__ stddev,
                                                   const float* __restrict__ outputs,
                                                   float* __restrict__ out) {
    int b = blockIdx.x, t = threadIdx.x;
    int lane = t & 31, warp = t >> 5;
    const float NI = neg_inf();
    int uni = g_flag;

    __shared__ int   s_tiles[TCAP];
    __shared__ int   s_nt, s_cnt;
    __shared__ int   sred[16];
    __shared__ uint32_t s_cand[NCAP];
    __shared__ float s_clp[NCAP];
    __shared__ float s_fv[TOPK];
    __shared__ int   s_fi[TOPK];
    __shared__ float s_w[TOPK];
    __shared__ float part[2 * 256];

    // ---- stage 1: cur = key of the NCAND-th largest tile max (16 vote rounds) ----
    uint32_t tk = hkey((uint32_t)__half_as_ushort(g_tmax[(size_t)b * NTILES + t]));
    uint32_t cur = 0;
    #pragma unroll 1
    for (int bit = 15; bit >= 0; --bit) {
        uint32_t T = cur | (1u << bit);
        int n = __syncthreads_count(tk >= T);
        if (n >= NCAND) cur = T;
    }
    if (t == 0) { s_nt = 0; s_cnt = 0; }
    __syncthreads();
    if (tk >= cur) {
        int p = atomicAdd(&s_nt, 1);
        if (p < TCAP) s_tiles[p] = t;
    }
    if (t < NCAP) s_clp[t] = NI;
    __syncthreads();
    int ntl = s_nt < TCAP ? s_nt : TCAP;
    int total = ntl * 64;          // u32 words across selected tiles

    // ---- stage 2: collect values with key >= cur directly (no second search) ----
    const uint32_t* row32 = (const uint32_t*)(g_lh + (size_t)b * Kc);
    #pragma unroll 4
    for (int i = 0; i < 16; i++) {
        int w = t + (i << 9);
        if (w < total) {
            int tile = s_tiles[w >> 6];
            uint32_t k2 = key2(row32[tile * 64 + (w & 63)]);
            uint32_t klo = k2 & 0xFFFFu, khi = k2 >> 16;
            uint32_t idx = (uint32_t)(tile * 128 + (w & 63) * 2);
            if (klo >= cur) {
                int p = atomicAdd(&s_cnt, 1);
                if (p < NCAP) s_cand[p] = (klo << 16) | idx;
            }
            if (khi >= cur) {
                int p = atomicAdd(&s_cnt, 1);
                if (p < NCAP) s_cand[p] = (khi << 16) | (idx + 1);
            }
        }
    }
    __syncthreads();
    int M = s_cnt;

    if (M > NCAP) {
        // ---- exact fallback (overflow; probability ~0): full 16-bit threshold search ----
        uint32_t u[16];
        #pragma unroll
        for (int i = 0; i < 16; i++) {
            int w = t + (i << 9);
            u[i] = (w < total) ? key2(row32[s_tiles[w >> 6] * 64 + (w & 63)]) : 0x03FF03FFu;
        }
        uint32_t cur16 = 0;
        #pragma unroll 1
        for (int bit = 15; bit >= 0; --bit) {
            uint32_t T = cur16 | (1u << bit);
            int c = 0;
            #pragma unroll
            for (int i = 0; i < 16; i++)
                c += ((u[i] & 0xFFFFu) >= T) + ((u[i] >> 16) >= T);
            #pragma unroll
            for (int off = 16; off > 0; off >>= 1)
                c += __shfl_xor_sync(0xffffffffu, c, off);
            __syncthreads();
            if (lane == 0) sred[warp] = c;
            __syncthreads();
            int n = 0;
            #pragma unroll
            for (int w2 = 0; w2 < 16; w2++) n += sred[w2];
            if (n >= NCAND) cur16 = T;
        }
        if (t == 0) s_cnt = 0;
        __syncthreads();
        #pragma unroll
        for (int i = 0; i < 16; i++) {
            int w = t + (i << 9);
            if (w < total) {
                uint32_t klo = u[i] & 0xFFFFu, khi = u[i] >> 16;
                uint32_t idx = (uint32_t)(s_tiles[w >> 6] * 128 + (w & 63) * 2);
                if (klo >= cur16) {
                    int p = atomicAdd(&s_cnt, 1);
                    if (p < NCAP) s_cand[p] = (klo << 16) | idx;
                }
                if (khi >= cur16) {
                    int p = atomicAdd(&s_cnt, 1);
                    if (p < NCAP) s_cand[p] = (khi << 16) | (idx + 1);
                }
            }
        }
        __syncthreads();
        M = s_cnt < NCAP ? s_cnt : NCAP;
    }

    // ---- exact fp32 rescore (one warp per candidate) ----
    for (int cc = warp; cc < M; cc += 16) {
        int c = (int)(s_cand[cc] & 0xFFFFu);
        float sq = 0.0f, sl = 0.0f;
        if (uni) {
            #pragma unroll
            for (int jj = 0; jj < 8; jj++) {
                int d = lane + (jj << 5);
                float m  = mean[(size_t)c * Dc + d];
                float xv = x[(size_t)b * Dc + d];
                float df = xv - m;
                sq = fmaf(df, df, sq);
            }
        } else {
            #pragma unroll
            for (int jj = 0; jj < 8; jj++) {
                int d = lane + (jj << 5);
                float m  = mean[(size_t)c * Dc + d];
                float sd = stddev[(size_t)c * Dc + d];
                float xv = x[(size_t)b * Dc + d];
                float iv = 1.0f / (sd * sd);
                float df = xv - m;
                sq = fmaf(df * df, iv, sq);
                sl += logf(sd);
            }
        }
        #pragma unroll
        for (int off = 16; off > 0; off >>= 1) {
            sq += __shfl_xor_sync(0xffffffffu, sq, off);
            sl += __shfl_xor_sync(0xffffffffu, sl, off);
        }
        if (lane == 0) s_clp[cc] = -0.5f * sq - sl - HALF_D_LOG2PI;
    }
    __syncthreads();

    // ---- exact top-32 of up to NCAP rescored values (warp 0, 4 slots/lane) ----
    if (warp == 0) {
        float va[4]; int ia[4];
        #pragma unroll
        for (int q = 0; q < 4; q++) { ia[q] = lane + q * 32; va[q] = s_clp[ia[q]]; }
        for (int r = 0; r < TOPK; r++) {
            float m = va[0]; int mi = ia[0];
            #pragma unroll
            for (int q = 1; q < 4; q++)
                if (va[q] > m) { m = va[q]; mi = ia[q]; }
            float bm = m; int bi = mi;
            #pragma unroll
            for (int off = 16; off > 0; off >>= 1) {
                float ov = __shfl_down_sync(0xffffffffu, bm, off);
                int   oi = __shfl_down_sync(0xffffffffu, bi, off);
                if (ov > bm) { bm = ov; bi = oi; }
            }
            bm = __shfl_sync(0xffffffffu, bm, 0);
            bi = __shfl_sync(0xffffffffu, bi, 0);
            if (lane == 0) { s_fv[r] = bm; s_fi[r] = (int)(s_cand[bi] & 0xFFFFu); }
            #pragma unroll
            for (int q = 0; q < 4; q++) if (ia[q] == bi) va[q] = NI;
        }
    }
    __syncthreads();

    if (t < TOPK) {
        float e = expf(s_fv[t] - s_fv[0]);
        float s = e;
        #pragma unroll
        for (int off = 16; off > 0; off >>= 1)
            s += __shfl_xor_sync(0xffffffffu, s, off);
        s_w[t] = e / s;
    }
    __syncthreads();

    int o = t & 255, g = t >> 8;   // g in {0,1}
    float p = 0.0f;
    #pragma unroll
    for (int j = 0; j < 16; j++) {
        int jj = g * 16 + j;
        p = fmaf(s_w[jj], outputs[(size_t)s_fi[jj] * Oc + o], p);
    }
    part[g * 256 + o] = p;
    __syncthreads();
    if (t < 256)
        out[(size_t)b * Oc + t] = part[t] + part[256 + t];
}

// ---------------- launch ----------------
extern "C" void kernel_launch(void* const* d_in, const int* in_sizes, int n_in,
                              void* d_out, int out_size) {
    const float* x       = (const float*)d_in[0];
    const float* mean    = (const float*)d_in[1];
    const float* stddev  = (const float*)d_in[2];
    const float* outputs = (const float*)d_in[3];
    float* out = (float*)d_out;

    cudaFuncSetAttribute(gemm_kernel, cudaFuncAttributeMaxDynamicSharedMemorySize, GEMM_SMEM);

    prep_x_kernel<<<Bc, Dc>>>(x);
    prep_w_kernel<<<Kc / 8, 256>>>(mean, stddev);
    prep_w_fix_kernel<<<Kc / 8, 256>>>(stddev);
    gemm_kernel<<<dim3(Bc / 128, Kc / 128), 128, GEMM_SMEM>>>();
    topk_kernel<<<Bc, 512>>>(x, mean, stddev, outputs, out);
}

// round 17
// speedup vs baseline: 1.7858x; 1.0671x over previous
#include <cuda_runtime.h>
#include <cuda_bf16.h>
#include <cuda_fp16.h>
#include <math.h>
#include <stdint.h>

#define Kc 65536
#define Dc 256
#define Oc 256
#define Bc 1024
#define TOPK 32
#define NCAND 48
#define NCAP 128
#define NTILES 512
#define TCAP 128
#define TWOD 512
#define SHIFT_FULL 491.25f
#define SHIFT_UNI  363.25f
#define HALF_D_LOG2PI 235.2482645f   // 0.5 * 256 * ln(2*pi)

// ---------------- device scratch ----------------
__device__ __nv_bfloat16 g_xb[(size_t)Bc * TWOD];        // 1 MB  [x | -0.5x^2]
__device__ __nv_bfloat16 g_wb[(size_t)Kc * TWOD];        // 64 MB [m*iv | iv]
__device__ float         g_bias[Kc];
__device__ __half        g_lh[(size_t)Bc * Kc];          // 128 MB shifted logits
__device__ __half        g_tmax[(size_t)Bc * NTILES];    // 1 MB per-row per-tile max (fp16)
__device__ int           g_flag;                          // 1 => stddev == 1 everywhere

__device__ __forceinline__ float neg_inf() { return __int_as_float(0xff800000); }

__device__ __forceinline__ uint32_t smem_u32(const void* p) {
    uint32_t a;
    asm("{ .reg .u64 t; cvta.to.shared.u64 t, %1; cvt.u32.u64 %0, t; }" : "=r"(a) : "l"(p));
    return a;
}
__device__ __forceinline__ void cp_async16(uint32_t dst, const void* src) {
    asm volatile("cp.async.cg.shared.global [%0], [%1], 16;" :: "r"(dst), "l"(src));
}
#define CP_COMMIT() asm volatile("cp.async.commit_group;" ::: "memory")
#define CP_WAIT(n)  asm volatile("cp.async.wait_group %0;" :: "n"(n) : "memory")

#define LDSM_X4(r, addr) \
    asm volatile("ldmatrix.sync.aligned.m8n8.x4.shared.b16 {%0,%1,%2,%3}, [%4];" \
        : "=r"((r)[0]), "=r"((r)[1]), "=r"((r)[2]), "=r"((r)[3]) : "r"(addr))

__device__ __forceinline__ void mma16816(float* c, const uint32_t* a, uint32_t b0, uint32_t b1) {
    asm volatile("mma.sync.aligned.m16n8k16.row.col.f32.bf16.bf16.f32 "
        "{%0,%1,%2,%3}, {%4,%5,%6,%7}, {%8,%9}, {%0,%1,%2,%3};"
        : "+f"(c[0]), "+f"(c[1]), "+f"(c[2]), "+f"(c[3])
        : "r"(a[0]), "r"(a[1]), "r"(a[2]), "r"(a[3]), "r"(b0), "r"(b1));
}

// both halves of a half2 word -> order-preserving 16-bit keys
__device__ __forceinline__ uint32_t key2(uint32_t h2) {
    uint32_t s = h2 & 0x80008000u;
    uint32_t m = 0x80008000u | ((s >> 15) * 0x7FFFu);
    return h2 ^ m;
}

// ---------------- prep kernels ----------------
__global__ void prep_x_kernel(const float* __restrict__ x) {
    int b = blockIdx.x, d = threadIdx.x;
    float v = x[b * Dc + d];
    g_xb[(size_t)b * TWOD + d]      = __float2bfloat16(v);
    g_xb[(size_t)b * TWOD + Dc + d] = __float2bfloat16(-0.5f * v * v);
    if (b == 0 && d == 0) g_flag = 1;   // reset each launch (graph-replay safe)
}

// warp per k-row, lane handles 8 elements; writes only the m*iv half (32 MB)
__global__ void __launch_bounds__(256) prep_w_kernel(const float* __restrict__ mean,
                                                     const float* __restrict__ stddev) {
    int warp = threadIdx.x >> 5, lane = threadIdx.x & 31;
    int k = blockIdx.x * 8 + warp;
    int e = lane * 8;
    const float* mp = mean   + (size_t)k * Dc + e;
    const float* sp = stddev + (size_t)k * Dc + e;
    float4 ma = *(const float4*)mp,      mb = *(const float4*)(mp + 4);
    float4 sa = *(const float4*)sp,      sb = *(const float4*)(sp + 4);

    bool nonuni = (sa.x != 1.0f) | (sa.y != 1.0f) | (sa.z != 1.0f) | (sa.w != 1.0f) |
                  (sb.x != 1.0f) | (sb.y != 1.0f) | (sb.z != 1.0f) | (sb.w != 1.0f);
    if (nonuni) g_flag = 0;

    float m8[8] = {ma.x, ma.y, ma.z, ma.w, mb.x, mb.y, mb.z, mb.w};
    float s8[8] = {sa.x, sa.y, sa.z, sa.w, sb.x, sb.y, sb.z, sb.w};
    float part = 0.0f;
    __nv_bfloat16 w8[8];
    #pragma unroll
    for (int i = 0; i < 8; i++) {
        float iv = 1.0f / (s8[i] * s8[i]);
        float miv = m8[i] * iv;
        w8[i] = __float2bfloat16(miv);
        part = fmaf(-0.5f * m8[i], miv, part);
    }
    if (nonuni) {
        #pragma unroll
        for (int i = 0; i < 8; i++) part -= logf(s8[i]);
    }
    *(uint4*)&g_wb[(size_t)k * TWOD + e] = *(uint4*)w8;

    #pragma unroll
    for (int off = 16; off > 0; off >>= 1)
        part += __shfl_xor_sync(0xffffffffu, part, off);
    if (lane == 0) g_bias[k] = part - HALF_D_LOG2PI;
}

// fix-up: writes the iv half; grid-stride, runs only when some stddev != 1
__global__ void __launch_bounds__(256) prep_w_fix_kernel(const float* __restrict__ stddev) {
    if (g_flag) return;
    int warp = threadIdx.x >> 5, lane = threadIdx.x & 31;
    for (int blk = blockIdx.x; blk < Kc / 8; blk += gridDim.x) {
        int k = blk * 8 + warp;
        int e = lane * 8;
        const float* sp = stddev + (size_t)k * Dc + e;
        float4 sa = *(const float4*)sp, sb = *(const float4*)(sp + 4);
        float s8[8] = {sa.x, sa.y, sa.z, sa.w, sb.x, sb.y, sb.z, sb.w};
        __nv_bfloat16 w8[8];
        #pragma unroll
        for (int i = 0; i < 8; i++)
            w8[i] = __float2bfloat16(1.0f / (s8[i] * s8[i]));
        *(uint4*)&g_wb[(size_t)k * TWOD + Dc + e] = *(uint4*)w8;
    }
}

// ---------------- mma.sync bf16 GEMM (+ per-tile row max) ----------------
// 128x128 CTA tile, 4 warps (2x2), 64x64 warp tiles, BK=64, XOR-swizzled
// 128B smem rows; fragment double-buffering across ks-halves and iterations.
#define NSTAGE 3
#define STAGE_BYTES 32768              // A[128x128B] + B[128x128B]
#define GEMM_SMEM (NSTAGE * STAGE_BYTES)
#define STGROW 272                      // staging row stride (bytes)

__device__ __forceinline__ void load_stage(uint32_t sbase, int st, int m0, int n0, int k0, int tid) {
    uint32_t ab = sbase + st * STAGE_BYTES;
    uint32_t bb = ab + 16384;
    #pragma unroll
    for (int i = 0; i < 8; i++) {
        int lin = tid + (i << 7);
        int row = lin >> 3, ch = lin & 7;
        uint32_t off = (uint32_t)row * 128u + ((uint32_t)(ch ^ (row & 7)) << 4);
        cp_async16(ab + off, g_xb + (size_t)(m0 + row) * TWOD + k0 + ch * 8);
        cp_async16(bb + off, g_wb + (size_t)(n0 + row) * TWOD + k0 + ch * 8);
    }
    CP_COMMIT();
}

#define LDSM_FRAGS(afr, bfr, stb, ks) do { \
    uint32_t _ab = (stb) + a_base + axk[ks]; \
    uint32_t _bb = (stb) + 16384 + b_base + bxk[ks]; \
    _Pragma("unroll") \
    for (int _mt = 0; _mt < 4; _mt++) \
        LDSM_X4((afr)[_mt], _ab + _mt * 2048); \
    _Pragma("unroll") \
    for (int _np = 0; _np < 4; _np++) \
        LDSM_X4((bfr)[_np], _bb + _np * 2048); \
} while (0)

#define MMA_ALL(afr, bfr) do { \
    _Pragma("unroll") \
    for (int _mt = 0; _mt < 4; _mt++) \
        _Pragma("unroll") \
        for (int _nt = 0; _nt < 8; _nt++) \
            mma16816(acc[_mt][_nt], (afr)[_mt], \
                     (bfr)[_nt >> 1][(_nt & 1) * 2], (bfr)[_nt >> 1][(_nt & 1) * 2 + 1]); \
} while (0)

__global__ void __launch_bounds__(128, 2) gemm_kernel() {
    extern __shared__ char smem[];
    __shared__ float smax[128][2];
    uint32_t sbase = smem_u32(smem);
    int tid = threadIdx.x, wid = tid >> 5, lane = tid & 31;
    int m0 = blockIdx.x * 128;            // M fastest: consecutive CTAs share B tile
    int n0 = blockIdx.y * 128;
    int wm = wid >> 1, wn = wid & 1;

    int uni = g_flag;
    int KTB = uni ? 4 : 8;                // 64-wide k slices
    float SHIFTV = uni ? SHIFT_UNI : SHIFT_FULL;

    float acc[4][8][4];
    #pragma unroll
    for (int mt = 0; mt < 4; mt++)
        #pragma unroll
        for (int nt = 0; nt < 8; nt++)
            #pragma unroll
            for (int q = 0; q < 4; q++) acc[mt][nt][q] = 0.0f;

    load_stage(sbase, 0, m0, n0, 0, tid);
    load_stage(sbase, 1, m0, n0, 64, tid);

    // XOR-swizzled fragment addressing (per-thread constants)
    int a_r = wm * 64 + (lane & 15);
    int hiA = lane >> 4;
    uint32_t a_base = (uint32_t)a_r * 128u;
    int r7a = a_r & 7;
    int b_r = wn * 64 + (lane & 7) + ((lane >> 4) << 3);
    int hiB = (lane >> 3) & 1;
    uint32_t b_base = (uint32_t)b_r * 128u;
    int r7b = b_r & 7;
    uint32_t axk[4], bxk[4];
    #pragma unroll
    for (int ks = 0; ks < 4; ks++) {
        axk[ks] = (uint32_t)((ks * 2 + hiA) ^ r7a) << 4;
        bxk[ks] = (uint32_t)((ks * 2 + hiB) ^ r7b) << 4;
    }

    uint32_t afr0[4][4], bfr0[4][4];
    uint32_t afr1[4][4], bfr1[4][4];

    CP_WAIT(1);            // stage 0 complete (own groups)
    __syncthreads();
    LDSM_FRAGS(afr0, bfr0, sbase, 0);

    #pragma unroll 1
    for (int it = 0; it < KTB; it++) {
        __syncthreads();   // all reads of slot (it+2)%3 (from iter it-1) done
        if (it + 2 < KTB) load_stage(sbase, (it + 2) % NSTAGE, m0, n0, (it + 2) * 64, tid);
        else CP_COMMIT();
        CP_WAIT(1);        // stages it and it+1 complete (own groups)

        uint32_t stb = sbase + (it % NSTAGE) * STAGE_BYTES;

        LDSM_FRAGS(afr1, bfr1, stb, 1);
        MMA_ALL(afr0, bfr0);
        LDSM_FRAGS(afr0, bfr0, stb, 2);
        MMA_ALL(afr1, bfr1);
        LDSM_FRAGS(afr1, bfr1, stb, 3);
        MMA_ALL(afr0, bfr0);
        if (it + 1 < KTB) {
            uint32_t stb2 = sbase + ((it + 1) % NSTAGE) * STAGE_BYTES;
            LDSM_FRAGS(afr0, bfr0, stb2, 0);
        }
        MMA_ALL(afr1, bfr1);
    }
    CP_WAIT(0);
    __syncthreads();   // all ldmatrix done: staging may overwrite pipeline smem

    const float NI = neg_inf();
    float rmA[4], rmB[4];
    #pragma unroll
    for (int mt = 0; mt < 4; mt++) { rmA[mt] = NI; rmB[mt] = NI; }

    // stage converted half2 into smem (conflict-free: 272B row stride)
    #pragma unroll
    for (int nt = 0; nt < 8; nt++) {
        int col = wn * 64 + nt * 8 + (lane & 3) * 2;
        float2 bb2 = *(const float2*)&g_bias[n0 + col];
        float bx = bb2.x + SHIFTV, by = bb2.y + SHIFTV;
        #pragma unroll
        for (int mt = 0; mt < 4; mt++) {
            int rowl = wm * 64 + mt * 16 + (lane >> 2);
            float a0 = acc[mt][nt][0] + bx, a1 = acc[mt][nt][1] + by;
            float a2 = acc[mt][nt][2] + bx, a3 = acc[mt][nt][3] + by;
            rmA[mt] = fmaxf(rmA[mt], fmaxf(a0, a1));
            rmB[mt] = fmaxf(rmB[mt], fmaxf(a2, a3));
            *(__half2*)(smem + rowl * STGROW + col * 2)       = __floats2half2_rn(a0, a1);
            *(__half2*)(smem + (rowl + 8) * STGROW + col * 2) = __floats2half2_rn(a2, a3);
        }
    }

    #pragma unroll
    for (int mt = 0; mt < 4; mt++) {
        #pragma unroll
        for (int off = 1; off < 4; off <<= 1) {
            rmA[mt] = fmaxf(rmA[mt], __shfl_xor_sync(0xffffffffu, rmA[mt], off));
            rmB[mt] = fmaxf(rmB[mt], __shfl_xor_sync(0xffffffffu, rmB[mt], off));
        }
        if ((lane & 3) == 0) {
            int lr = wm * 64 + mt * 16 + (lane >> 2);
            smax[lr][wn]     = rmA[mt];
            smax[lr + 8][wn] = rmB[mt];
        }
    }
    __syncthreads();

    // coalesced copy-out: 128 rows x 256B = 2048 uint4, 16 per thread
    #pragma unroll
    for (int i = 0; i < 16; i++) {
        int lin = tid + (i << 7);
        int r = lin >> 4, q = lin & 15;
        uint4 v = *(const uint4*)(smem + r * STGROW + q * 16);
        *(uint4*)(g_lh + (size_t)(m0 + r) * Kc + n0 + q * 8) = v;
    }

    {
        float m = fmaxf(smax[tid][0], smax[tid][1]);
        // rn is monotonic: half(max fp32) == max over tile of half(v)
        g_tmax[(size_t)(m0 + tid) * NTILES + blockIdx.y] = __float2half(m);
    }
}

// ---------------- topk: warp-scope threshold + direct collect + exact rescore ----------------
__global__ void __launch_bounds__(512) topk_kernel(const float* __restrict__ x,
                                                   const float* __restrict__ mean,
                                                   const float* __restrict__ stddev,
                                                   const float* __restrict__ outputs,
                                                   float* __restrict__ out) {
    int b = blockIdx.x, t = threadIdx.x;
    int lane = t & 31, warp = t >> 5;
    const float NI = neg_inf();
    int uni = g_flag;

    __shared__ int   s_tiles[TCAP];
    __shared__ int   s_nt, s_cnt;
    __shared__ uint32_t s_curk;
    __shared__ int   sred[16];
    __shared__ uint32_t s_cand[NCAP];
    __shared__ float s_clp[NCAP];
    __shared__ float s_fv[TOPK];
    __shared__ int   s_fi[TOPK];
    __shared__ float s_w[TOPK];
    __shared__ float part[2 * 256];

    // ---- stage 1 (warp 0 only): threshold = key of the NCAND-th largest tile max,
    //      via register-resident search with __reduce_add_sync — no block barriers.
    if (warp == 0) {
        const uint4* tm = (const uint4*)(g_tmax + (size_t)b * NTILES);
        uint4 p0 = tm[lane * 2];
        uint4 p1 = tm[lane * 2 + 1];
        uint32_t w8[8] = { key2(p0.x), key2(p0.y), key2(p0.z), key2(p0.w),
                           key2(p1.x), key2(p1.y), key2(p1.z), key2(p1.w) };
        uint32_t cur = 0;
        #pragma unroll 1
        for (int bit = 15; bit >= 0; --bit) {
            uint32_t T = cur | (1u << bit);
            int c = 0;
            #pragma unroll
            for (int j = 0; j < 8; j++)
                c += ((w8[j] & 0xFFFFu) >= T) + ((w8[j] >> 16) >= T);
            c = __reduce_add_sync(0xffffffffu, c);
            if (c >= NCAND) cur = T;
        }
        // ballot-compaction of selected tiles (tile = lane*16 + j)
        int base = 0;
        #pragma unroll
        for (int j = 0; j < 16; j++) {
            uint32_t kj = (j & 1) ? (w8[j >> 1] >> 16) : (w8[j >> 1] & 0xFFFFu);
            uint32_t msk = __ballot_sync(0xffffffffu, kj >= cur);
            if (kj >= cur) {
                int pos = base + __popc(msk & ((1u << lane) - 1u));
                if (pos < TCAP) s_tiles[pos] = lane * 16 + j;
            }
            base += __popc(msk);
        }
        if (lane == 0) {
            s_nt = base < TCAP ? base : TCAP;
            s_curk = cur;
            s_cnt = 0;
        }
    }
    if (t < NCAP) s_clp[t] = NI;
    __syncthreads();
    uint32_t cur = s_curk;
    int total = s_nt * 64;         // u32 words across selected tiles

    // ---- stage 2: collect values with key >= cur directly ----
    const uint32_t* row32 = (const uint32_t*)(g_lh + (size_t)b * Kc);
    #pragma unroll 4
    for (int i = 0; i < 16; i++) {
        int w = t + (i << 9);
        if (w < total) {
            int tile = s_tiles[w >> 6];
            uint32_t k2 = key2(row32[tile * 64 + (w & 63)]);
            uint32_t klo = k2 & 0xFFFFu, khi = k2 >> 16;
            uint32_t idx = (uint32_t)(tile * 128 + (w & 63) * 2);
            if (klo >= cur) {
                int p = atomicAdd(&s_cnt, 1);
                if (p < NCAP) s_cand[p] = (klo << 16) | idx;
            }
            if (khi >= cur) {
                int p = atomicAdd(&s_cnt, 1);
                if (p < NCAP) s_cand[p] = (khi << 16) | (idx + 1);
            }
        }
    }
    __syncthreads();
    int M = s_cnt;

    if (M > NCAP) {
        // ---- exact fallback (overflow; ~never): threshold search re-reading logits ----
        uint32_t cur16 = 0;
        #pragma unroll 1
        for (int bit = 15; bit >= 0; --bit) {
            uint32_t T = cur16 | (1u << bit);
            int c = 0;
            for (int i = 0; i < 16; i++) {
                int w = t + (i << 9);
                if (w < total) {
                    uint32_t k2 = key2(row32[s_tiles[w >> 6] * 64 + (w & 63)]);
                    c += ((k2 & 0xFFFFu) >= T) + ((k2 >> 16) >= T);
                }
            }
            #pragma unroll
            for (int off = 16; off > 0; off >>= 1)
                c += __shfl_xor_sync(0xffffffffu, c, off);
            __syncthreads();
            if (lane == 0) sred[warp] = c;
            __syncthreads();
            int n = 0;
            #pragma unroll
            for (int w2 = 0; w2 < 16; w2++) n += sred[w2];
            if (n >= NCAND) cur16 = T;
        }
        if (t == 0) s_cnt = 0;
        __syncthreads();
        for (int i = 0; i < 16; i++) {
            int w = t + (i << 9);
            if (w < total) {
                int tile = s_tiles[w >> 6];
                uint32_t k2 = key2(row32[tile * 64 + (w & 63)]);
                uint32_t klo = k2 & 0xFFFFu, khi = k2 >> 16;
                uint32_t idx = (uint32_t)(tile * 128 + (w & 63) * 2);
                if (klo >= cur16) {
                    int p = atomicAdd(&s_cnt, 1);
                    if (p < NCAP) s_cand[p] = (klo << 16) | idx;
                }
                if (khi >= cur16) {
                    int p = atomicAdd(&s_cnt, 1);
                    if (p < NCAP) s_cand[p] = (khi << 16) | (idx + 1);
                }
            }
        }
        __syncthreads();
        M = s_cnt < NCAP ? s_cnt : NCAP;
    }

    // ---- exact fp32 rescore ----
    if (uni) {
        // preload 4 candidates per warp: 32 independent LDGs in flight
        float xv8[8];
        #pragma unroll
        for (int jj = 0; jj < 8; jj++)
            xv8[jj] = x[(size_t)b * Dc + lane + (jj << 5)];
        int cs[4];
        #pragma unroll
        for (int q = 0; q < 4; q++) {
            int cc = warp + q * 16;
            cs[q] = (cc < M) ? (int)(s_cand[cc] & 0xFFFFu) : 0;
        }
        float mv[4][8];
        #pragma unroll
        for (int q = 0; q < 4; q++)
            #pragma unroll
            for (int jj = 0; jj < 8; jj++)
                mv[q][jj] = mean[(size_t)cs[q] * Dc + lane + (jj << 5)];
        #pragma unroll
        for (int q = 0; q < 4; q++) {
            float sq = 0.0f;
            #pragma unroll
            for (int jj = 0; jj < 8; jj++) {
                float df = xv8[jj] - mv[q][jj];
                sq = fmaf(df, df, sq);
            }
            #pragma unroll
            for (int off = 16; off > 0; off >>= 1)
                sq += __shfl_xor_sync(0xffffffffu, sq, off);
            int cc = warp + q * 16;
            if (lane == 0 && cc < M)
                s_clp[cc] = -0.5f * sq - HALF_D_LOG2PI;
        }
        // remainder (M > 64)
        for (int cc = warp + 64; cc < M; cc += 16) {
            int c = (int)(s_cand[cc] & 0xFFFFu);
            float sq = 0.0f;
            #pragma unroll
            for (int jj = 0; jj < 8; jj++) {
                float df = xv8[jj] - mean[(size_t)c * Dc + lane + (jj << 5)];
                sq = fmaf(df, df, sq);
            }
            #pragma unroll
            for (int off = 16; off > 0; off >>= 1)
                sq += __shfl_xor_sync(0xffffffffu, sq, off);
            if (lane == 0) s_clp[cc] = -0.5f * sq - HALF_D_LOG2PI;
        }
    } else {
        for (int cc = warp; cc < M; cc += 16) {
            int c = (int)(s_cand[cc] & 0xFFFFu);
            float sq = 0.0f, sl = 0.0f;
            #pragma unroll
            for (int jj = 0; jj < 8; jj++) {
                int d = lane + (jj << 5);
                float m  = mean[(size_t)c * Dc + d];
                float sd = stddev[(size_t)c * Dc + d];
                float xv = x[(size_t)b * Dc + d];
                float iv = 1.0f / (sd * sd);
                float df = xv - m;
                sq = fmaf(df * df, iv, sq);
                sl += logf(sd);
            }
            #pragma unroll
            for (int off = 16; off > 0; off >>= 1) {
                sq += __shfl_xor_sync(0xffffffffu, sq, off);
                sl += __shfl_xor_sync(0xffffffffu, sl, off);
            }
            if (lane == 0) s_clp[cc] = -0.5f * sq - sl - HALF_D_LOG2PI;
        }
    }
    __syncthreads();

    // ---- exact top-32 of up to NCAP rescored values (warp 0, 4 slots/lane) ----
    if (warp == 0) {
        float va[4]; int ia[4];
        #pragma unroll
        for (int q = 0; q < 4; q++) { ia[q] = lane + q * 32; va[q] = s_clp[ia[q]]; }
        for (int r = 0; r < TOPK; r++) {
            float m = va[0]; int mi = ia[0];
            #pragma unroll
            for (int q = 1; q < 4; q++)
                if (va[q] > m) { m = va[q]; mi = ia[q]; }
            float bm = m; int bi = mi;
            #pragma unroll
            for (int off = 16; off > 0; off >>= 1) {
                float ov = __shfl_down_sync(0xffffffffu, bm, off);
                int   oi = __shfl_down_sync(0xffffffffu, bi, off);
                if (ov > bm) { bm = ov; bi = oi; }
            }
            bm = __shfl_sync(0xffffffffu, bm, 0);
            bi = __shfl_sync(0xffffffffu, bi, 0);
            if (lane == 0) { s_fv[r] = bm; s_fi[r] = (int)(s_cand[bi] & 0xFFFFu); }
            #pragma unroll
            for (int q = 0; q < 4; q++) if (ia[q] == bi) va[q] = NI;
        }
    }
    __syncthreads();

    if (t < TOPK) {
        float e = expf(s_fv[t] - s_fv[0]);
        float s = e;
        #pragma unroll
        for (int off = 16; off > 0; off >>= 1)
            s += __shfl_xor_sync(0xffffffffu, s, off);
        s_w[t] = e / s;
    }
    __syncthreads();

    int o = t & 255, g = t >> 8;   // g in {0,1}
    float p = 0.0f;
    #pragma unroll
    for (int j = 0; j < 16; j++) {
        int jj = g * 16 + j;
        p = fmaf(s_w[jj], outputs[(size_t)s_fi[jj] * Oc + o], p);
    }
    part[g * 256 + o] = p;
    __syncthreads();
    if (t < 256)
        out[(size_t)b * Oc + t] = part[t] + part[256 + t];
}

// ---------------- launch ----------------
extern "C" void kernel_launch(void* const* d_in, const int* in_sizes, int n_in,
                              void* d_out, int out_size) {
    const float* x       = (const float*)d_in[0];
    const float* mean    = (const float*)d_in[1];
    const float* stddev  = (const float*)d_in[2];
    const float* outputs = (const float*)d_in[3];
    float* out = (float*)d_out;

    cudaFuncSetAttribute(gemm_kernel, cudaFuncAttributeMaxDynamicSharedMemorySize, GEMM_SMEM);

    prep_x_kernel<<<Bc, Dc>>>(x);
    prep_w_kernel<<<Kc / 8, 256>>>(mean, stddev);
    prep_w_fix_kernel<<<512, 256>>>(stddev);
    gemm_kernel<<<dim3(Bc / 128, Kc / 128), 128, GEMM_SMEM>>>();
    topk_kernel<<<Bc, 512>>>(x, mean, stddev, outputs, out);
}